// round 1
// baseline (speedup 1.0000x reference)
#include <cuda_runtime.h>
#include <cuda_bf16.h>
#include <cstdint>

// Problem constants
#define BATCH 8
#define SEQ   2048
#define DMODEL 1024
#define DHEAD 64

// Scratch (allocation-free rule: __device__ globals)
__device__ float g_Q[BATCH * SEQ * DHEAD];
__device__ float g_K[BATCH * SEQ * DHEAD];
__device__ float g_V[BATCH * SEQ * DHEAD];
__device__ float g_S[(size_t)BATCH * SEQ * SEQ];   // 128 MB scores scratch
__device__ float g_colmax[BATCH * SEQ];
__device__ float g_colinv[BATCH * SEQ];

// ---------------------------------------------------------------------------
// Kernel 1: fused QKV projection.  out[row, 0:64] = x[row,:] @ W + b
// grid (SEQ*BATCH/64, 3), block 256.  64x64 output tile per block, k-chunk 32.
// ---------------------------------------------------------------------------
__global__ __launch_bounds__(256) void proj_kernel(
    const float* __restrict__ x,
    const float* __restrict__ Wq, const float* __restrict__ bq,
    const float* __restrict__ Wk, const float* __restrict__ bk,
    const float* __restrict__ Wv, const float* __restrict__ bv)
{
    const int which = blockIdx.y;
    const float* W    = (which == 0) ? Wq : (which == 1) ? Wk : Wv;
    const float* bias = (which == 0) ? bq : (which == 1) ? bk : bv;
    float* out        = (which == 0) ? g_Q : (which == 1) ? g_K : g_V;

    __shared__ float sA[64][33];   // x tile: 64 rows x 32 k
    __shared__ float sB[32][65];   // W tile: 32 k x 64 cols

    const int t  = threadIdx.x;
    const int tx = t & 15;         // 0..15 -> output col group
    const int ty = t >> 4;         // 0..15 -> output row group
    const int row0 = blockIdx.x * 64;

    float acc[4][4] = {};

    for (int k0 = 0; k0 < DMODEL; k0 += 32) {
        // load 64x32 x tile (coalesced: 32-float rows)
        #pragma unroll
        for (int i = 0; i < 8; i++) {
            int idx = t + i * 256;
            int r = idx >> 5, c = idx & 31;
            sA[r][c] = x[(row0 + r) * DMODEL + k0 + c];
        }
        // load 32x64 W tile
        #pragma unroll
        for (int i = 0; i < 8; i++) {
            int idx = t + i * 256;
            int r = idx >> 6, c = idx & 63;
            sB[r][c] = W[(k0 + r) * DHEAD + c];
        }
        __syncthreads();
        #pragma unroll
        for (int kk = 0; kk < 32; kk++) {
            float a[4], b[4];
            #pragma unroll
            for (int i = 0; i < 4; i++) a[i] = sA[ty * 4 + i][kk];
            #pragma unroll
            for (int j = 0; j < 4; j++) b[j] = sB[kk][tx * 4 + j];
            #pragma unroll
            for (int i = 0; i < 4; i++)
                #pragma unroll
                for (int j = 0; j < 4; j++)
                    acc[i][j] = fmaf(a[i], b[j], acc[i][j]);
        }
        __syncthreads();
    }

    #pragma unroll
    for (int i = 0; i < 4; i++) {
        int r = row0 + ty * 4 + i;
        float4 v;
        v.x = acc[i][0] + bias[tx * 4 + 0];
        v.y = acc[i][1] + bias[tx * 4 + 1];
        v.z = acc[i][2] + bias[tx * 4 + 2];
        v.w = acc[i][3] + bias[tx * 4 + 3];
        *reinterpret_cast<float4*>(&out[r * DHEAD + tx * 4]) = v;
    }
}

// ---------------------------------------------------------------------------
// Kernel 2: S[b,i,j] = (Q[b,i,:] . K[b,j,:]) * 0.125
// grid (SEQ/64, SEQ/64, BATCH), block 256.  64x64 tile, full k=64 in smem.
// ---------------------------------------------------------------------------
__global__ __launch_bounds__(256) void scores_kernel()
{
    const int b    = blockIdx.z;
    const int row0 = blockIdx.y * 64;   // i
    const int col0 = blockIdx.x * 64;   // j

    __shared__ float sQ[64][65];
    __shared__ float sK[64][65];

    const int t  = threadIdx.x;
    const int tx = t & 15;
    const int ty = t >> 4;

    const float* Qb = g_Q + b * SEQ * DHEAD;
    const float* Kb = g_K + b * SEQ * DHEAD;

    #pragma unroll
    for (int i = 0; i < 16; i++) {
        int idx = t + i * 256;          // 64*64 = 4096 elements
        int r = idx >> 6, c = idx & 63;
        sQ[r][c] = Qb[(row0 + r) * DHEAD + c];
        sK[r][c] = Kb[(col0 + r) * DHEAD + c];
    }
    __syncthreads();

    float acc[4][4] = {};
    #pragma unroll
    for (int k = 0; k < DHEAD; k++) {
        float a[4], bb[4];
        #pragma unroll
        for (int i = 0; i < 4; i++) a[i]  = sQ[ty * 4 + i][k];
        #pragma unroll
        for (int j = 0; j < 4; j++) bb[j] = sK[tx * 4 + j][k];
        #pragma unroll
        for (int i = 0; i < 4; i++)
            #pragma unroll
            for (int j = 0; j < 4; j++)
                acc[i][j] = fmaf(a[i], bb[j], acc[i][j]);
    }

    float* Sb = g_S + (size_t)b * SEQ * SEQ;
    #pragma unroll
    for (int i = 0; i < 4; i++) {
        int r = row0 + ty * 4 + i;
        float4 v;
        v.x = acc[i][0] * 0.125f;
        v.y = acc[i][1] * 0.125f;
        v.z = acc[i][2] * 0.125f;
        v.w = acc[i][3] * 0.125f;
        *reinterpret_cast<float4*>(&Sb[(size_t)r * SEQ + col0 + tx * 4]) = v;
    }
}

// ---------------------------------------------------------------------------
// Kernel 3: per-column (axis=1 / i-axis) softmax stats: max + sum-exp over i.
// grid (SEQ/32, BATCH), block (32, 8).  Thread (tx,ty) owns column j0+tx,
// rows i = ty, ty+8, ...  Coalesced row reads.
// ---------------------------------------------------------------------------
__global__ __launch_bounds__(256) void colstats_kernel()
{
    const int b  = blockIdx.y;
    const int j  = blockIdx.x * 32 + threadIdx.x;
    const int ty = threadIdx.y;

    const float* Sb = g_S + (size_t)b * SEQ * SEQ;

    float m = -1e30f, s = 0.0f;
    for (int i = ty; i < SEQ; i += 8) {
        float v  = Sb[(size_t)i * SEQ + j];
        float nm = fmaxf(m, v);
        s = s * __expf(m - nm) + __expf(v - nm);
        m = nm;
    }

    __shared__ float sm[8][33];
    __shared__ float ss[8][33];
    sm[ty][threadIdx.x] = m;
    ss[ty][threadIdx.x] = s;
    __syncthreads();

    if (ty == 0) {
        #pragma unroll
        for (int r = 1; r < 8; r++) {
            float m2 = sm[r][threadIdx.x], s2 = ss[r][threadIdx.x];
            float nm = fmaxf(m, m2);
            s = s * __expf(m - nm) + s2 * __expf(m2 - nm);
            m = nm;
        }
        g_colmax[b * SEQ + j] = m;
        g_colinv[b * SEQ + j] = 1.0f / s;
    }
}

// ---------------------------------------------------------------------------
// Kernel 4: O[b,i,:] = sum_j P[i,j] * V[j,:],  P[i,j]=exp(S[i,j]-m_j)*inv_j
// grid (SEQ/64, BATCH), block 256.  64 rows x 64(DH) tile, j-chunk 32.
// Each thread loads a fixed column-within-chunk (t&31) so (m_j, inv_j) live
// in two registers per chunk.
// ---------------------------------------------------------------------------
__global__ __launch_bounds__(256) void out_kernel(float* __restrict__ out)
{
    const int b    = blockIdx.y;
    const int row0 = blockIdx.x * 64;

    __shared__ float sP[64][33];
    __shared__ float sV[32][65];

    const int t  = threadIdx.x;
    const int tx = t & 15;
    const int ty = t >> 4;
    const int cc = t & 31;          // column-within-chunk this thread loads
    const int rr = t >> 5;          // base row for loads

    const float* Sb = g_S + (size_t)b * SEQ * SEQ;
    const float* Vb = g_V + b * SEQ * DHEAD;

    float acc[4][4] = {};

    for (int j0 = 0; j0 < SEQ; j0 += 32) {
        float mj = g_colmax[b * SEQ + j0 + cc];
        float ij = g_colinv[b * SEQ + j0 + cc];
        #pragma unroll
        for (int i = 0; i < 8; i++) {
            int r = rr + i * 8;
            float v = Sb[(size_t)(row0 + r) * SEQ + j0 + cc];
            sP[r][cc] = __expf(v - mj) * ij;
        }
        #pragma unroll
        for (int i = 0; i < 8; i++) {
            int idx = t + i * 256;
            int r = idx >> 6, c = idx & 63;
            sV[r][c] = Vb[(j0 + r) * DHEAD + c];
        }
        __syncthreads();
        #pragma unroll
        for (int kk = 0; kk < 32; kk++) {
            float a[4], bb[4];
            #pragma unroll
            for (int i = 0; i < 4; i++) a[i]  = sP[ty * 4 + i][kk];
            #pragma unroll
            for (int j = 0; j < 4; j++) bb[j] = sV[kk][tx * 4 + j];
            #pragma unroll
            for (int i = 0; i < 4; i++)
                #pragma unroll
                for (int j = 0; j < 4; j++)
                    acc[i][j] = fmaf(a[i], bb[j], acc[i][j]);
        }
        __syncthreads();
    }

    float* Ob = out + b * SEQ * DHEAD;
    #pragma unroll
    for (int i = 0; i < 4; i++) {
        int r = row0 + ty * 4 + i;
        float4 v;
        v.x = acc[i][0]; v.y = acc[i][1]; v.z = acc[i][2]; v.w = acc[i][3];
        *reinterpret_cast<float4*>(&Ob[r * DHEAD + tx * 4]) = v;
    }
}

// ---------------------------------------------------------------------------
extern "C" void kernel_launch(void* const* d_in, const int* in_sizes, int n_in,
                              void* d_out, int out_size)
{
    const float* x  = (const float*)d_in[0];
    const float* Wq = (const float*)d_in[1];
    const float* bq = (const float*)d_in[2];
    const float* Wk = (const float*)d_in[3];
    const float* bk = (const float*)d_in[4];
    const float* Wv = (const float*)d_in[5];
    const float* bv = (const float*)d_in[6];
    float* out = (float*)d_out;

    // 1) QKV projections
    {
        dim3 grid(BATCH * SEQ / 64, 3);
        proj_kernel<<<grid, 256>>>(x, Wq, bq, Wk, bk, Wv, bv);
    }
    // 2) Scores
    {
        dim3 grid(SEQ / 64, SEQ / 64, BATCH);
        scores_kernel<<<grid, 256>>>();
    }
    // 3) Column softmax stats (softmax over axis=1)
    {
        dim3 grid(SEQ / 32, BATCH);
        colstats_kernel<<<grid, dim3(32, 8)>>>();
    }
    // 4) Output GEMM with on-the-fly softmax normalization
    {
        dim3 grid(SEQ / 64, BATCH);
        out_kernel<<<grid, 256>>>(out);
    }
}

// round 2
// speedup vs baseline: 1.0020x; 1.0020x over previous
#include <cuda_runtime.h>
#include <cuda_bf16.h>
#include <cstdint>

// Problem constants
#define BATCH 8
#define SEQ   2048
#define DMODEL 1024
#define DHEAD 64

// Scratch (allocation-free rule: __device__ globals)
__device__ float g_Q[BATCH * SEQ * DHEAD];
__device__ float g_K[BATCH * SEQ * DHEAD];
__device__ float g_V[BATCH * SEQ * DHEAD];
__device__ float g_S[(size_t)BATCH * SEQ * SEQ];   // 128 MB scores scratch
__device__ float g_colmax[BATCH * SEQ];
__device__ float g_colinv[BATCH * SEQ];

// ---------------------------------------------------------------------------
// Kernel 1: fused QKV projection.  out[row, 0:64] = x[row,:] @ W + b
// grid (SEQ*BATCH/64, 3), block 256.  64x64 output tile per block, k-chunk 32.
// ---------------------------------------------------------------------------
__global__ __launch_bounds__(256) void proj_kernel(
    const float* __restrict__ x,
    const float* __restrict__ Wq, const float* __restrict__ bq,
    const float* __restrict__ Wk, const float* __restrict__ bk,
    const float* __restrict__ Wv, const float* __restrict__ bv)
{
    const int which = blockIdx.y;
    const float* W    = (which == 0) ? Wq : (which == 1) ? Wk : Wv;
    const float* bias = (which == 0) ? bq : (which == 1) ? bk : bv;
    float* out        = (which == 0) ? g_Q : (which == 1) ? g_K : g_V;

    __shared__ float sA[64][33];   // x tile: 64 rows x 32 k
    __shared__ float sB[32][65];   // W tile: 32 k x 64 cols

    const int t  = threadIdx.x;
    const int tx = t & 15;         // 0..15 -> output col group
    const int ty = t >> 4;         // 0..15 -> output row group
    const int row0 = blockIdx.x * 64;

    float acc[4][4] = {};

    for (int k0 = 0; k0 < DMODEL; k0 += 32) {
        // load 64x32 x tile (coalesced: 32-float rows)
        #pragma unroll
        for (int i = 0; i < 8; i++) {
            int idx = t + i * 256;
            int r = idx >> 5, c = idx & 31;
            sA[r][c] = x[(row0 + r) * DMODEL + k0 + c];
        }
        // load 32x64 W tile
        #pragma unroll
        for (int i = 0; i < 8; i++) {
            int idx = t + i * 256;
            int r = idx >> 6, c = idx & 63;
            sB[r][c] = W[(k0 + r) * DHEAD + c];
        }
        __syncthreads();
        #pragma unroll
        for (int kk = 0; kk < 32; kk++) {
            float a[4], b[4];
            #pragma unroll
            for (int i = 0; i < 4; i++) a[i] = sA[ty * 4 + i][kk];
            #pragma unroll
            for (int j = 0; j < 4; j++) b[j] = sB[kk][tx * 4 + j];
            #pragma unroll
            for (int i = 0; i < 4; i++)
                #pragma unroll
                for (int j = 0; j < 4; j++)
                    acc[i][j] = fmaf(a[i], b[j], acc[i][j]);
        }
        __syncthreads();
    }

    #pragma unroll
    for (int i = 0; i < 4; i++) {
        int r = row0 + ty * 4 + i;
        float4 v;
        v.x = acc[i][0] + bias[tx * 4 + 0];
        v.y = acc[i][1] + bias[tx * 4 + 1];
        v.z = acc[i][2] + bias[tx * 4 + 2];
        v.w = acc[i][3] + bias[tx * 4 + 3];
        *reinterpret_cast<float4*>(&out[r * DHEAD + tx * 4]) = v;
    }
}

// ---------------------------------------------------------------------------
// Kernel 2: S[b,i,j] = (Q[b,i,:] . K[b,j,:]) * 0.125
// grid (SEQ/64, SEQ/64, BATCH), block 256.  64x64 tile, full k=64 in smem.
// ---------------------------------------------------------------------------
__global__ __launch_bounds__(256) void scores_kernel()
{
    const int b    = blockIdx.z;
    const int row0 = blockIdx.y * 64;   // i
    const int col0 = blockIdx.x * 64;   // j

    __shared__ float sQ[64][65];
    __shared__ float sK[64][65];

    const int t  = threadIdx.x;
    const int tx = t & 15;
    const int ty = t >> 4;

    const float* Qb = g_Q + b * SEQ * DHEAD;
    const float* Kb = g_K + b * SEQ * DHEAD;

    #pragma unroll
    for (int i = 0; i < 16; i++) {
        int idx = t + i * 256;          // 64*64 = 4096 elements
        int r = idx >> 6, c = idx & 63;
        sQ[r][c] = Qb[(row0 + r) * DHEAD + c];
        sK[r][c] = Kb[(col0 + r) * DHEAD + c];
    }
    __syncthreads();

    float acc[4][4] = {};
    #pragma unroll
    for (int k = 0; k < DHEAD; k++) {
        float a[4], bb[4];
        #pragma unroll
        for (int i = 0; i < 4; i++) a[i]  = sQ[ty * 4 + i][k];
        #pragma unroll
        for (int j = 0; j < 4; j++) bb[j] = sK[tx * 4 + j][k];
        #pragma unroll
        for (int i = 0; i < 4; i++)
            #pragma unroll
            for (int j = 0; j < 4; j++)
                acc[i][j] = fmaf(a[i], bb[j], acc[i][j]);
    }

    float* Sb = g_S + (size_t)b * SEQ * SEQ;
    #pragma unroll
    for (int i = 0; i < 4; i++) {
        int r = row0 + ty * 4 + i;
        float4 v;
        v.x = acc[i][0] * 0.125f;
        v.y = acc[i][1] * 0.125f;
        v.z = acc[i][2] * 0.125f;
        v.w = acc[i][3] * 0.125f;
        *reinterpret_cast<float4*>(&Sb[(size_t)r * SEQ + col0 + tx * 4]) = v;
    }
}

// ---------------------------------------------------------------------------
// Kernel 3: per-column (axis=1 / i-axis) softmax stats: max + sum-exp over i.
// grid (SEQ/32, BATCH), block (32, 8).  Thread (tx,ty) owns column j0+tx,
// rows i = ty, ty+8, ...  Coalesced row reads.
// ---------------------------------------------------------------------------
__global__ __launch_bounds__(256) void colstats_kernel()
{
    const int b  = blockIdx.y;
    const int j  = blockIdx.x * 32 + threadIdx.x;
    const int ty = threadIdx.y;

    const float* Sb = g_S + (size_t)b * SEQ * SEQ;

    float m = -1e30f, s = 0.0f;
    for (int i = ty; i < SEQ; i += 8) {
        float v  = Sb[(size_t)i * SEQ + j];
        float nm = fmaxf(m, v);
        s = s * __expf(m - nm) + __expf(v - nm);
        m = nm;
    }

    __shared__ float sm[8][33];
    __shared__ float ss[8][33];
    sm[ty][threadIdx.x] = m;
    ss[ty][threadIdx.x] = s;
    __syncthreads();

    if (ty == 0) {
        #pragma unroll
        for (int r = 1; r < 8; r++) {
            float m2 = sm[r][threadIdx.x], s2 = ss[r][threadIdx.x];
            float nm = fmaxf(m, m2);
            s = s * __expf(m - nm) + s2 * __expf(m2 - nm);
            m = nm;
        }
        g_colmax[b * SEQ + j] = m;
        g_colinv[b * SEQ + j] = 1.0f / s;
    }
}

// ---------------------------------------------------------------------------
// Kernel 4: O[b,i,:] = sum_j P[i,j] * V[j,:],  P[i,j]=exp(S[i,j]-m_j)*inv_j
// grid (SEQ/64, BATCH), block 256.  64 rows x 64(DH) tile, j-chunk 32.
// Each thread loads a fixed column-within-chunk (t&31) so (m_j, inv_j) live
// in two registers per chunk.
// ---------------------------------------------------------------------------
__global__ __launch_bounds__(256) void out_kernel(float* __restrict__ out)
{
    const int b    = blockIdx.y;
    const int row0 = blockIdx.x * 64;

    __shared__ float sP[64][33];
    __shared__ float sV[32][65];

    const int t  = threadIdx.x;
    const int tx = t & 15;
    const int ty = t >> 4;
    const int cc = t & 31;          // column-within-chunk this thread loads
    const int rr = t >> 5;          // base row for loads

    const float* Sb = g_S + (size_t)b * SEQ * SEQ;
    const float* Vb = g_V + b * SEQ * DHEAD;

    float acc[4][4] = {};

    for (int j0 = 0; j0 < SEQ; j0 += 32) {
        float mj = g_colmax[b * SEQ + j0 + cc];
        float ij = g_colinv[b * SEQ + j0 + cc];
        #pragma unroll
        for (int i = 0; i < 8; i++) {
            int r = rr + i * 8;
            float v = Sb[(size_t)(row0 + r) * SEQ + j0 + cc];
            sP[r][cc] = __expf(v - mj) * ij;
        }
        #pragma unroll
        for (int i = 0; i < 8; i++) {
            int idx = t + i * 256;
            int r = idx >> 6, c = idx & 63;
            sV[r][c] = Vb[(j0 + r) * DHEAD + c];
        }
        __syncthreads();
        #pragma unroll
        for (int kk = 0; kk < 32; kk++) {
            float a[4], bb[4];
            #pragma unroll
            for (int i = 0; i < 4; i++) a[i]  = sP[ty * 4 + i][kk];
            #pragma unroll
            for (int j = 0; j < 4; j++) bb[j] = sV[kk][tx * 4 + j];
            #pragma unroll
            for (int i = 0; i < 4; i++)
                #pragma unroll
                for (int j = 0; j < 4; j++)
                    acc[i][j] = fmaf(a[i], bb[j], acc[i][j]);
        }
        __syncthreads();
    }

    float* Ob = out + b * SEQ * DHEAD;
    #pragma unroll
    for (int i = 0; i < 4; i++) {
        int r = row0 + ty * 4 + i;
        float4 v;
        v.x = acc[i][0]; v.y = acc[i][1]; v.z = acc[i][2]; v.w = acc[i][3];
        *reinterpret_cast<float4*>(&Ob[r * DHEAD + tx * 4]) = v;
    }
}

// ---------------------------------------------------------------------------
extern "C" void kernel_launch(void* const* d_in, const int* in_sizes, int n_in,
                              void* d_out, int out_size)
{
    const float* x  = (const float*)d_in[0];
    const float* Wq = (const float*)d_in[1];
    const float* bq = (const float*)d_in[2];
    const float* Wk = (const float*)d_in[3];
    const float* bk = (const float*)d_in[4];
    const float* Wv = (const float*)d_in[5];
    const float* bv = (const float*)d_in[6];
    float* out = (float*)d_out;

    // 1) QKV projections
    {
        dim3 grid(BATCH * SEQ / 64, 3);
        proj_kernel<<<grid, 256>>>(x, Wq, bq, Wk, bk, Wv, bv);
    }
    // 2) Scores
    {
        dim3 grid(SEQ / 64, SEQ / 64, BATCH);
        scores_kernel<<<grid, 256>>>();
    }
    // 3) Column softmax stats (softmax over axis=1)
    {
        dim3 grid(SEQ / 32, BATCH);
        colstats_kernel<<<grid, dim3(32, 8)>>>();
    }
    // 4) Output GEMM with on-the-fly softmax normalization
    {
        dim3 grid(SEQ / 64, BATCH);
        out_kernel<<<grid, 256>>>(out);
    }
}

// round 4
// speedup vs baseline: 1.8625x; 1.8587x over previous
#include <cuda_runtime.h>
#include <cuda_bf16.h>
#include <cstdint>

#define BATCH 8
#define SEQ   2048
#define DM    1024
#define DH    64
#define NTOK  (BATCH * SEQ)
#define ITILES 16

// ---------------- device scratch ----------------
__device__ __nv_bfloat16 g_Wth[3 * DH * DM];   // [mat*64+c][k]
__device__ __nv_bfloat16 g_Wtl[3 * DH * DM];
__device__ __nv_bfloat16 g_Qh[NTOK * DH], g_Ql[NTOK * DH];
__device__ __nv_bfloat16 g_Kh[NTOK * DH], g_Kl[NTOK * DH];
__device__ __nv_bfloat16 g_Vth[BATCH * DH * SEQ];  // [b][d][i]
__device__ __nv_bfloat16 g_Vtl[BATCH * DH * SEQ];
__device__ float g_S[(size_t)BATCH * SEQ * SEQ];
__device__ float g_pmax[BATCH * ITILES * SEQ];
__device__ float g_psum[BATCH * ITILES * SEQ];
__device__ float g_cm[BATCH * SEQ];
__device__ float g_ci[BATCH * SEQ];

// ---------------- helpers ----------------
__device__ __forceinline__ uint32_t s_u32(const void* p) {
    uint32_t a;
    asm("{ .reg .u64 t; cvta.to.shared.u64 t, %1; cvt.u32.u64 %0, t; }" : "=r"(a) : "l"(p));
    return a;
}
#define LDSM4(r0, r1, r2, r3, addr) \
    asm volatile("ldmatrix.sync.aligned.m8n8.x4.shared.b16 {%0,%1,%2,%3}, [%4];" \
                 : "=r"(r0), "=r"(r1), "=r"(r2), "=r"(r3) : "r"(addr))

__device__ __forceinline__ void mma_bf16(float* c, const uint32_t* a, const uint32_t* b) {
    asm volatile(
        "mma.sync.aligned.m16n8k16.row.col.f32.bf16.bf16.f32 "
        "{%0,%1,%2,%3}, {%4,%5,%6,%7}, {%8,%9}, {%0,%1,%2,%3};"
        : "+f"(c[0]), "+f"(c[1]), "+f"(c[2]), "+f"(c[3])
        : "r"(a[0]), "r"(a[1]), "r"(a[2]), "r"(a[3]), "r"(b[0]), "r"(b[1]));
}

__device__ __forceinline__ void bsplit(float v, unsigned short& h, unsigned short& l) {
    __nv_bfloat16 bh = __float2bfloat16(v);
    __nv_bfloat16 bl = __float2bfloat16(v - __bfloat162float(bh));
    h = __bfloat16_as_ushort(bh); l = __bfloat16_as_ushort(bl);
}
__device__ __forceinline__ uint32_t pk2(unsigned short a, unsigned short b) {
    return (uint32_t)a | ((uint32_t)b << 16);
}

// ---------------- split/transpose W ----------------
__global__ __launch_bounds__(256) void split_w_kernel(
    const float* __restrict__ Wq, const float* __restrict__ Wk, const float* __restrict__ Wv) {
    int mt = blockIdx.y;
    const float* W = (mt == 0) ? Wq : (mt == 1) ? Wk : Wv;
    int idx = blockIdx.x * 256 + threadIdx.x;   // 65536 = 1024*64
    int k = idx >> 6, c = idx & 63;
    unsigned short h, l;
    bsplit(W[k * DH + c], h, l);
    g_Wth[(mt * 64 + c) * DM + k] = __ushort_as_bfloat16(h);
    g_Wtl[(mt * 64 + c) * DM + k] = __ushort_as_bfloat16(l);
}

// ---------------- fused QKV projection ----------------
// grid 128, block 512 (16 warps, 4x4). C tile [128 rows][192 cols], K-chunk 64.
// smem bf16: Ah[128][72], Al, Bh[192][72], Bl  (92160 B)
__global__ __launch_bounds__(512) void proj_kernel(
    const float* __restrict__ x, const float* __restrict__ bq,
    const float* __restrict__ bk, const float* __restrict__ bv) {
    extern __shared__ char smem[];
    const int tid = threadIdx.x, lane = tid & 31, w = tid >> 5;
    const int row0 = blockIdx.x * 128;
    const int bb = row0 >> 11, iloc = row0 & 2047;

    __nv_bfloat16* Ah = (__nv_bfloat16*)smem;           // 9216 elems
    __nv_bfloat16* Al = Ah + 128 * 72;
    __nv_bfloat16* Bh = Al + 128 * 72;                  // 13824 elems
    __nv_bfloat16* Bl = Bh + 192 * 72;
    const uint32_t sAh = s_u32(Ah), sAl = s_u32(Al), sBh = s_u32(Bh), sBl = s_u32(Bl);

    const int wm = w & 3, wn = w >> 2;                  // rows wm*32, cols wn*48
    float acc[2][6][4];
    #pragma unroll
    for (int i = 0; i < 2; i++)
        #pragma unroll
        for (int j = 0; j < 6; j++)
            #pragma unroll
            for (int q = 0; q < 4; q++) acc[i][j][q] = 0.f;

    for (int kc = 0; kc < 16; kc++) {
        const int k0g = kc * 64;
        // x fp32 load + split -> Ah/Al
        {
            int r = tid >> 2, c0 = (tid & 3) * 16;
            const float4* src = (const float4*)(x + (size_t)(row0 + r) * DM + k0g + c0);
            unsigned short hs[16], ls[16];
            #pragma unroll
            for (int q = 0; q < 4; q++) {
                float4 v = src[q];
                bsplit(v.x, hs[q*4+0], ls[q*4+0]); bsplit(v.y, hs[q*4+1], ls[q*4+1]);
                bsplit(v.z, hs[q*4+2], ls[q*4+2]); bsplit(v.w, hs[q*4+3], ls[q*4+3]);
            }
            uint4* dh = (uint4*)(Ah + r * 72 + c0);
            uint4* dl = (uint4*)(Al + r * 72 + c0);
            dh[0] = make_uint4(pk2(hs[0],hs[1]), pk2(hs[2],hs[3]), pk2(hs[4],hs[5]), pk2(hs[6],hs[7]));
            dh[1] = make_uint4(pk2(hs[8],hs[9]), pk2(hs[10],hs[11]), pk2(hs[12],hs[13]), pk2(hs[14],hs[15]));
            dl[0] = make_uint4(pk2(ls[0],ls[1]), pk2(ls[2],ls[3]), pk2(ls[4],ls[5]), pk2(ls[6],ls[7]));
            dl[1] = make_uint4(pk2(ls[8],ls[9]), pk2(ls[10],ls[11]), pk2(ls[12],ls[13]), pk2(ls[14],ls[15]));
        }
        // W^T bf16 loads
        #pragma unroll
        for (int p = 0; p < 3; p++) {
            int lin = p * 512 + tid, r = lin >> 3, q = lin & 7;
            *(uint4*)(Bh + r * 72 + q * 8) =
                *(const uint4*)((const char*)g_Wth + ((size_t)r * DM + k0g) * 2 + q * 16);
            *(uint4*)(Bl + r * 72 + q * 8) =
                *(const uint4*)((const char*)g_Wtl + ((size_t)r * DM + k0g) * 2 + q * 16);
        }
        __syncthreads();
        #pragma unroll
        for (int ks = 0; ks < 4; ks++) {
            const int k0 = ks * 16;
            uint32_t a_h[2][4], a_l[2][4];
            #pragma unroll
            for (int mf = 0; mf < 2; mf++) {
                uint32_t off = (uint32_t)((wm * 32 + mf * 16 + (lane & 15)) * 72 +
                                          k0 + ((lane >> 4) << 3)) * 2;
                LDSM4(a_h[mf][0], a_h[mf][1], a_h[mf][2], a_h[mf][3], sAh + off);
                LDSM4(a_l[mf][0], a_l[mf][1], a_l[mf][2], a_l[mf][3], sAl + off);
            }
            uint32_t b_h[6][2], b_l[6][2];
            #pragma unroll
            for (int nb = 0; nb < 3; nb++) {
                uint32_t off = (uint32_t)((wn * 48 + nb * 16 + (lane & 7) + ((lane >> 4) << 3)) * 72 +
                                          k0 + (((lane >> 3) & 1) << 3)) * 2;
                LDSM4(b_h[2*nb][0], b_h[2*nb][1], b_h[2*nb+1][0], b_h[2*nb+1][1], sBh + off);
                LDSM4(b_l[2*nb][0], b_l[2*nb][1], b_l[2*nb+1][0], b_l[2*nb+1][1], sBl + off);
            }
            #pragma unroll
            for (int mf = 0; mf < 2; mf++)
                #pragma unroll
                for (int nf = 0; nf < 6; nf++) {
                    mma_bf16(acc[mf][nf], a_h[mf], b_h[nf]);
                    mma_bf16(acc[mf][nf], a_h[mf], b_l[nf]);
                    mma_bf16(acc[mf][nf], a_l[mf], b_h[nf]);
                }
        }
        __syncthreads();
    }

    // epilogue: Q/K direct split stores; V staged transposed in smem
    __nv_bfloat16* sVh = Bh;   // [64][136] = 8704 elems, fits
    __nv_bfloat16* sVl = Bl;
    #pragma unroll
    for (int mf = 0; mf < 2; mf++)
        #pragma unroll
        for (int nf = 0; nf < 6; nf++) {
            int gc = wn * 48 + nf * 8 + (lane & 3) * 2;
            int mt = gc >> 6, cm = gc & 63;
            int r0 = wm * 32 + mf * 16 + (lane >> 2);
            #pragma unroll
            for (int h = 0; h < 2; h++) {
                int rl = r0 + h * 8;
                float v0 = acc[mf][nf][h * 2 + 0], v1 = acc[mf][nf][h * 2 + 1];
                unsigned short h0, l0, h1, l1;
                if (mt < 2) {
                    const float* bias = mt ? bk : bq;
                    bsplit(v0 + bias[cm], h0, l0);
                    bsplit(v1 + bias[cm + 1], h1, l1);
                    size_t o = (size_t)(row0 + rl) * DH + cm;
                    *(uint32_t*)((mt ? g_Kh : g_Qh) + o) = pk2(h0, h1);
                    *(uint32_t*)((mt ? g_Kl : g_Ql) + o) = pk2(l0, l1);
                } else {
                    bsplit(v0 + bv[cm], h0, l0);
                    bsplit(v1 + bv[cm + 1], h1, l1);
                    sVh[cm * 136 + rl] = __ushort_as_bfloat16(h0);
                    sVh[(cm + 1) * 136 + rl] = __ushort_as_bfloat16(h1);
                    sVl[cm * 136 + rl] = __ushort_as_bfloat16(l0);
                    sVl[(cm + 1) * 136 + rl] = __ushort_as_bfloat16(l1);
                }
            }
        }
    __syncthreads();
    #pragma unroll
    for (int p = 0; p < 2; p++) {
        int lin = p * 512 + tid, r = lin >> 4, q = lin & 15;
        size_t dst = ((size_t)(bb * 64 + r) * SEQ + iloc + q * 8) * 2;
        *(uint4*)((char*)g_Vth + dst) = *(uint4*)(sVh + r * 136 + q * 8);
        *(uint4*)((char*)g_Vtl + dst) = *(uint4*)(sVl + r * 136 + q * 8);
    }
}

// ---------------- scores + partial column stats ----------------
// grid (16,16,8), block 256 (8 warps 2x4). C tile [128][128], K=64.
// smem: Qh,Ql,Kh,Kl each [128][72] bf16 (73728 B); reused as Sst f32 pitch 132.
__global__ __launch_bounds__(256) void scores_kernel() {
    extern __shared__ char smem[];
    const int tid = threadIdx.x, lane = tid & 31, w = tid >> 5;
    const int jt = blockIdx.x, it = blockIdx.y, bb = blockIdx.z;
    const int i0 = it * 128, j0 = jt * 128;

    __nv_bfloat16* T = (__nv_bfloat16*)smem;
    __nv_bfloat16* arr[4] = { T, T + 9216, T + 18432, T + 27648 };  // Qh Ql Kh Kl
    const __nv_bfloat16* src[4] = { g_Qh, g_Ql, g_Kh, g_Kl };
    #pragma unroll
    for (int a = 0; a < 4; a++) {
        const int rb = bb * SEQ + ((a < 2) ? i0 : j0);
        #pragma unroll
        for (int p = 0; p < 4; p++) {
            int lin = p * 256 + tid, r = lin >> 3, q = lin & 7;
            *(uint4*)(arr[a] + r * 72 + q * 8) =
                *(const uint4*)((const char*)src[a] + ((size_t)(rb + r) * DH) * 2 + q * 16);
        }
    }
    __syncthreads();

    const uint32_t sQh = s_u32(arr[0]), sQl = s_u32(arr[1]);
    const uint32_t sKh = s_u32(arr[2]), sKl = s_u32(arr[3]);
    const int wm = w & 1, wn = w >> 1;          // rows wm*64, cols wn*32
    float acc[4][4][4];
    #pragma unroll
    for (int i = 0; i < 4; i++)
        #pragma unroll
        for (int j = 0; j < 4; j++)
            #pragma unroll
            for (int q = 0; q < 4; q++) acc[i][j][q] = 0.f;

    #pragma unroll
    for (int ks = 0; ks < 4; ks++) {
        const int k0 = ks * 16;
        uint32_t a_h[4][4], a_l[4][4];
        #pragma unroll
        for (int mf = 0; mf < 4; mf++) {
            uint32_t off = (uint32_t)((wm * 64 + mf * 16 + (lane & 15)) * 72 +
                                      k0 + ((lane >> 4) << 3)) * 2;
            LDSM4(a_h[mf][0], a_h[mf][1], a_h[mf][2], a_h[mf][3], sQh + off);
            LDSM4(a_l[mf][0], a_l[mf][1], a_l[mf][2], a_l[mf][3], sQl + off);
        }
        uint32_t b_h[4][2], b_l[4][2];
        #pragma unroll
        for (int nb = 0; nb < 2; nb++) {
            uint32_t off = (uint32_t)((wn * 32 + nb * 16 + (lane & 7) + ((lane >> 4) << 3)) * 72 +
                                      k0 + (((lane >> 3) & 1) << 3)) * 2;
            LDSM4(b_h[2*nb][0], b_h[2*nb][1], b_h[2*nb+1][0], b_h[2*nb+1][1], sKh + off);
            LDSM4(b_l[2*nb][0], b_l[2*nb][1], b_l[2*nb+1][0], b_l[2*nb+1][1], sKl + off);
        }
        #pragma unroll
        for (int mf = 0; mf < 4; mf++)
            #pragma unroll
            for (int nf = 0; nf < 4; nf++) {
                mma_bf16(acc[mf][nf], a_h[mf], b_h[nf]);
                mma_bf16(acc[mf][nf], a_h[mf], b_l[nf]);
                mma_bf16(acc[mf][nf], a_l[mf], b_h[nf]);
            }
    }
    __syncthreads();

    float* Sst = (float*)smem;      // pitch 132 (67584 B <= 73728)
    #pragma unroll
    for (int mf = 0; mf < 4; mf++)
        #pragma unroll
        for (int nf = 0; nf < 4; nf++) {
            int col = wn * 32 + nf * 8 + (lane & 3) * 2;
            int r0 = wm * 64 + mf * 16 + (lane >> 2);
            #pragma unroll
            for (int h = 0; h < 2; h++) {
                Sst[(r0 + h * 8) * 132 + col]     = acc[mf][nf][h * 2 + 0] * 0.125f;
                Sst[(r0 + h * 8) * 132 + col + 1] = acc[mf][nf][h * 2 + 1] * 0.125f;
            }
        }
    __syncthreads();
    // coalesced S store
    #pragma unroll
    for (int p = 0; p < 16; p++) {
        int lin = p * 256 + tid, r = lin >> 5, c4 = lin & 31;
        *(float4*)(g_S + ((size_t)(bb * SEQ + i0 + r)) * SEQ + j0 + c4 * 4) =
            *(float4*)(Sst + r * 132 + c4 * 4);
    }
    // per-column stats (col = tid, threads 0..127)
    if (tid < 128) {
        float m = -1e30f;
        #pragma unroll 8
        for (int i = 0; i < 128; i++) m = fmaxf(m, Sst[i * 132 + tid]);
        float s = 0.f;
        #pragma unroll 8
        for (int i = 0; i < 128; i++) s += __expf(Sst[i * 132 + tid] - m);
        g_pmax[(bb * ITILES + it) * SEQ + j0 + tid] = m;
        g_psum[(bb * ITILES + it) * SEQ + j0 + tid] = s;
    }
}

// ---------------- merge partial stats ----------------
__global__ __launch_bounds__(256) void merge_stats_kernel() {
    int idx = blockIdx.x * 256 + threadIdx.x;
    int bb = idx >> 11, j = idx & 2047;
    float m = -1e30f;
    #pragma unroll
    for (int it = 0; it < ITILES; it++)
        m = fmaxf(m, g_pmax[(bb * ITILES + it) * SEQ + j]);
    float s = 0.f;
    #pragma unroll
    for (int it = 0; it < ITILES; it++)
        s += g_psum[(bb * ITILES + it) * SEQ + j] *
             __expf(g_pmax[(bb * ITILES + it) * SEQ + j] - m);
    g_cm[idx] = m;
    g_ci[idx] = 1.0f / s;
}

// ---------------- output GEMM ----------------
// grid (16,8), block 256 (8 warps 4x2). C [128][64]; j-chunks of 64.
// smem: Ph[128][72], Pl, Vh[64][72], Vl (bf16) + sM/sI f32[64] -> 55808 B
__global__ __launch_bounds__(256) void out_kernel(float* __restrict__ out) {
    extern __shared__ char smem[];
    const int tid = threadIdx.x, lane = tid & 31, w = tid >> 5;
    const int it = blockIdx.x, bb = blockIdx.y;
    const int i0 = it * 128;

    __nv_bfloat16* Ph = (__nv_bfloat16*)smem;
    __nv_bfloat16* Pl = Ph + 9216;
    __nv_bfloat16* Vh = Pl + 9216;
    __nv_bfloat16* Vl = Vh + 4608;
    float* sM = (float*)(smem + 55296);
    float* sI = sM + 64;
    const uint32_t sPh = s_u32(Ph), sPl = s_u32(Pl), sVh = s_u32(Vh), sVl = s_u32(Vl);

    const int wm = w & 3, wn = w >> 2;          // rows wm*32, cols wn*32
    float acc[2][4][4];
    #pragma unroll
    for (int i = 0; i < 2; i++)
        #pragma unroll
        for (int j = 0; j < 4; j++)
            #pragma unroll
            for (int q = 0; q < 4; q++) acc[i][j][q] = 0.f;

    const int prow = tid >> 1, phalf = tid & 1;
    const float* Sr = g_S + ((size_t)(bb * SEQ + i0 + prow)) * SEQ;

    for (int c = 0; c < 32; c++) {
        const int j0 = c * 64;
        if (tid < 64) {
            sM[tid] = g_cm[bb * SEQ + j0 + tid];
            sI[tid] = g_ci[bb * SEQ + j0 + tid];
        }
        #pragma unroll
        for (int p = 0; p < 2; p++) {
            int lin = p * 256 + tid, r = lin >> 3, q = lin & 7;
            size_t so = (((size_t)(bb * 64 + r)) * SEQ + j0) * 2 + q * 16;
            *(uint4*)(Vh + r * 72 + q * 8) = *(const uint4*)((const char*)g_Vth + so);
            *(uint4*)(Vl + r * 72 + q * 8) = *(const uint4*)((const char*)g_Vtl + so);
        }
        __syncthreads();
        // build P: thread handles row prow, 32 cols at phalf*32
        {
            const float4* sp = (const float4*)(Sr + j0 + phalf * 32);
            const float* pM = sM + phalf * 32;
            const float* pI = sI + phalf * 32;
            unsigned short hs[32], ls[32];
            #pragma unroll
            for (int e = 0; e < 8; e++) {
                float4 v = sp[e];
                bsplit(__expf(v.x - pM[e*4+0]) * pI[e*4+0], hs[e*4+0], ls[e*4+0]);
                bsplit(__expf(v.y - pM[e*4+1]) * pI[e*4+1], hs[e*4+1], ls[e*4+1]);
                bsplit(__expf(v.z - pM[e*4+2]) * pI[e*4+2], hs[e*4+2], ls[e*4+2]);
                bsplit(__expf(v.w - pM[e*4+3]) * pI[e*4+3], hs[e*4+3], ls[e*4+3]);
            }
            uint4* dh = (uint4*)(Ph + prow * 72 + phalf * 32);
            uint4* dl = (uint4*)(Pl + prow * 72 + phalf * 32);
            #pragma unroll
            for (int e = 0; e < 4; e++) {
                dh[e] = make_uint4(pk2(hs[e*8],hs[e*8+1]), pk2(hs[e*8+2],hs[e*8+3]),
                                   pk2(hs[e*8+4],hs[e*8+5]), pk2(hs[e*8+6],hs[e*8+7]));
                dl[e] = make_uint4(pk2(ls[e*8],ls[e*8+1]), pk2(ls[e*8+2],ls[e*8+3]),
                                   pk2(ls[e*8+4],ls[e*8+5]), pk2(ls[e*8+6],ls[e*8+7]));
            }
        }
        __syncthreads();
        #pragma unroll
        for (int ks = 0; ks < 4; ks++) {
            const int k0 = ks * 16;
            uint32_t a_h[2][4], a_l[2][4];
            #pragma unroll
            for (int mf = 0; mf < 2; mf++) {
                uint32_t off = (uint32_t)((wm * 32 + mf * 16 + (lane & 15)) * 72 +
                                          k0 + ((lane >> 4) << 3)) * 2;
                LDSM4(a_h[mf][0], a_h[mf][1], a_h[mf][2], a_h[mf][3], sPh + off);
                LDSM4(a_l[mf][0], a_l[mf][1], a_l[mf][2], a_l[mf][3], sPl + off);
            }
            uint32_t b_h[4][2], b_l[4][2];
            #pragma unroll
            for (int nb = 0; nb < 2; nb++) {
                uint32_t off = (uint32_t)((wn * 32 + nb * 16 + (lane & 7) + ((lane >> 4) << 3)) * 72 +
                                          k0 + (((lane >> 3) & 1) << 3)) * 2;
                LDSM4(b_h[2*nb][0], b_h[2*nb][1], b_h[2*nb+1][0], b_h[2*nb+1][1], sVh + off);
                LDSM4(b_l[2*nb][0], b_l[2*nb][1], b_l[2*nb+1][0], b_l[2*nb+1][1], sVl + off);
            }
            #pragma unroll
            for (int mf = 0; mf < 2; mf++)
                #pragma unroll
                for (int nf = 0; nf < 4; nf++) {
                    mma_bf16(acc[mf][nf], a_h[mf], b_h[nf]);
                    mma_bf16(acc[mf][nf], a_h[mf], b_l[nf]);
                    mma_bf16(acc[mf][nf], a_l[mf], b_h[nf]);
                }
        }
        __syncthreads();
    }

    // epilogue: stage f32, pitch 68, then coalesced store
    float* Ost = (float*)smem;
    #pragma unroll
    for (int mf = 0; mf < 2; mf++)
        #pragma unroll
        for (int nf = 0; nf < 4; nf++) {
            int col = wn * 32 + nf * 8 + (lane & 3) * 2;
            int r0 = wm * 32 + mf * 16 + (lane >> 2);
            #pragma unroll
            for (int h = 0; h < 2; h++) {
                Ost[(r0 + h * 8) * 68 + col]     = acc[mf][nf][h * 2 + 0];
                Ost[(r0 + h * 8) * 68 + col + 1] = acc[mf][nf][h * 2 + 1];
            }
        }
    __syncthreads();
    #pragma unroll
    for (int p = 0; p < 8; p++) {
        int lin = p * 256 + tid, r = lin >> 4, c4 = lin & 15;
        *(float4*)(out + ((size_t)(bb * SEQ + i0 + r)) * DH + c4 * 4) =
            *(float4*)(Ost + r * 68 + c4 * 4);
    }
}

// ---------------- launch ----------------
extern "C" void kernel_launch(void* const* d_in, const int* in_sizes, int n_in,
                              void* d_out, int out_size)
{
    const float* x  = (const float*)d_in[0];
    const float* Wq = (const float*)d_in[1];
    const float* bq = (const float*)d_in[2];
    const float* Wk = (const float*)d_in[3];
    const float* bk = (const float*)d_in[4];
    const float* Wv = (const float*)d_in[5];
    const float* bv = (const float*)d_in[6];
    float* out = (float*)d_out;

    cudaFuncSetAttribute(proj_kernel,   cudaFuncAttributeMaxDynamicSharedMemorySize, 92160);
    cudaFuncSetAttribute(scores_kernel, cudaFuncAttributeMaxDynamicSharedMemorySize, 73728);
    cudaFuncSetAttribute(out_kernel,    cudaFuncAttributeMaxDynamicSharedMemorySize, 55808);

    split_w_kernel<<<dim3(256, 3), 256>>>(Wq, Wk, Wv);
    proj_kernel<<<128, 512, 92160>>>(x, bq, bk, bv);
    scores_kernel<<<dim3(16, 16, 8), 256, 73728>>>();
    merge_stats_kernel<<<64, 256>>>();
    out_kernel<<<dim3(16, 8), 256, 55808>>>(out);
}

// round 5
// speedup vs baseline: 2.6856x; 1.4419x over previous
#include <cuda_runtime.h>
#include <cuda_bf16.h>
#include <cstdint>

#define BATCH 8
#define SEQ   2048
#define DM    1024
#define DH    64
#define NTOK  (BATCH * SEQ)
#define ITILES 16

// ---------------- device scratch ----------------
__device__ __nv_bfloat16 g_Wth[3 * DH * DM];   // [mat*64+c][k]
__device__ __nv_bfloat16 g_Wtl[3 * DH * DM];
__device__ __nv_bfloat16 g_Qh[NTOK * DH], g_Ql[NTOK * DH];
__device__ __nv_bfloat16 g_Kh[NTOK * DH], g_Kl[NTOK * DH];
__device__ __nv_bfloat16 g_Vth[BATCH * DH * SEQ];  // [b][d][i]
__device__ __nv_bfloat16 g_Vtl[BATCH * DH * SEQ];
__device__ __nv_bfloat16 g_Eh[(size_t)NTOK * SEQ]; // exp(S) hi, row-major [b,i,j]
__device__ __nv_bfloat16 g_El[(size_t)NTOK * SEQ]; // exp(S) lo
__device__ float g_psum[BATCH * ITILES * SEQ];
__device__ float g_ci[BATCH * SEQ];

// ---------------- helpers ----------------
__device__ __forceinline__ uint32_t s_u32(const void* p) {
    uint32_t a;
    asm("{ .reg .u64 t; cvta.to.shared.u64 t, %1; cvt.u32.u64 %0, t; }" : "=r"(a) : "l"(p));
    return a;
}
#define LDSM4(r0, r1, r2, r3, addr) \
    asm volatile("ldmatrix.sync.aligned.m8n8.x4.shared.b16 {%0,%1,%2,%3}, [%4];" \
                 : "=r"(r0), "=r"(r1), "=r"(r2), "=r"(r3) : "r"(addr))
#define CPA16(dst, src) \
    asm volatile("cp.async.cg.shared.global [%0], [%1], 16;" :: "r"(dst), "l"(src))
#define CPA_COMMIT() asm volatile("cp.async.commit_group;" ::: "memory")
#define CPA_WAIT1()  asm volatile("cp.async.wait_group 1;" ::: "memory")
#define CPA_WAIT0()  asm volatile("cp.async.wait_group 0;" ::: "memory")

__device__ __forceinline__ void mma_bf16(float* c, const uint32_t* a, const uint32_t* b) {
    asm volatile(
        "mma.sync.aligned.m16n8k16.row.col.f32.bf16.bf16.f32 "
        "{%0,%1,%2,%3}, {%4,%5,%6,%7}, {%8,%9}, {%0,%1,%2,%3};"
        : "+f"(c[0]), "+f"(c[1]), "+f"(c[2]), "+f"(c[3])
        : "r"(a[0]), "r"(a[1]), "r"(a[2]), "r"(a[3]), "r"(b[0]), "r"(b[1]));
}

__device__ __forceinline__ void bsplit(float v, unsigned short& h, unsigned short& l) {
    __nv_bfloat16 bh = __float2bfloat16(v);
    __nv_bfloat16 bl = __float2bfloat16(v - __bfloat162float(bh));
    h = __bfloat16_as_ushort(bh); l = __bfloat16_as_ushort(bl);
}
__device__ __forceinline__ uint32_t pk2(unsigned short a, unsigned short b) {
    return (uint32_t)a | ((uint32_t)b << 16);
}

// ---------------- split/transpose W ----------------
__global__ __launch_bounds__(256) void split_w_kernel(
    const float* __restrict__ Wq, const float* __restrict__ Wk, const float* __restrict__ Wv) {
    int mt = blockIdx.y;
    const float* W = (mt == 0) ? Wq : (mt == 1) ? Wk : Wv;
    int idx = blockIdx.x * 256 + threadIdx.x;
    int k = idx >> 6, c = idx & 63;
    unsigned short h, l;
    bsplit(W[k * DH + c], h, l);
    g_Wth[(mt * 64 + c) * DM + k] = __ushort_as_bfloat16(h);
    g_Wtl[(mt * 64 + c) * DM + k] = __ushort_as_bfloat16(l);
}

// ---------------- fused QKV projection (unchanged structure) ----------------
__global__ __launch_bounds__(512) void proj_kernel(
    const float* __restrict__ x, const float* __restrict__ bq,
    const float* __restrict__ bk, const float* __restrict__ bv) {
    extern __shared__ char smem[];
    const int tid = threadIdx.x, lane = tid & 31, w = tid >> 5;
    const int row0 = blockIdx.x * 128;
    const int bb = row0 >> 11, iloc = row0 & 2047;

    __nv_bfloat16* Ah = (__nv_bfloat16*)smem;
    __nv_bfloat16* Al = Ah + 128 * 72;
    __nv_bfloat16* Bh = Al + 128 * 72;
    __nv_bfloat16* Bl = Bh + 192 * 72;
    const uint32_t sAh = s_u32(Ah), sAl = s_u32(Al), sBh = s_u32(Bh), sBl = s_u32(Bl);

    const int wm = w & 3, wn = w >> 2;
    float acc[2][6][4];
    #pragma unroll
    for (int i = 0; i < 2; i++)
        #pragma unroll
        for (int j = 0; j < 6; j++)
            #pragma unroll
            for (int q = 0; q < 4; q++) acc[i][j][q] = 0.f;

    for (int kc = 0; kc < 16; kc++) {
        const int k0g = kc * 64;
        {
            int r = tid >> 2, c0 = (tid & 3) * 16;
            const float4* src = (const float4*)(x + (size_t)(row0 + r) * DM + k0g + c0);
            unsigned short hs[16], ls[16];
            #pragma unroll
            for (int q = 0; q < 4; q++) {
                float4 v = src[q];
                bsplit(v.x, hs[q*4+0], ls[q*4+0]); bsplit(v.y, hs[q*4+1], ls[q*4+1]);
                bsplit(v.z, hs[q*4+2], ls[q*4+2]); bsplit(v.w, hs[q*4+3], ls[q*4+3]);
            }
            uint4* dh = (uint4*)(Ah + r * 72 + c0);
            uint4* dl = (uint4*)(Al + r * 72 + c0);
            dh[0] = make_uint4(pk2(hs[0],hs[1]), pk2(hs[2],hs[3]), pk2(hs[4],hs[5]), pk2(hs[6],hs[7]));
            dh[1] = make_uint4(pk2(hs[8],hs[9]), pk2(hs[10],hs[11]), pk2(hs[12],hs[13]), pk2(hs[14],hs[15]));
            dl[0] = make_uint4(pk2(ls[0],ls[1]), pk2(ls[2],ls[3]), pk2(ls[4],ls[5]), pk2(ls[6],ls[7]));
            dl[1] = make_uint4(pk2(ls[8],ls[9]), pk2(ls[10],ls[11]), pk2(ls[12],ls[13]), pk2(ls[14],ls[15]));
        }
        #pragma unroll
        for (int p = 0; p < 3; p++) {
            int lin = p * 512 + tid, r = lin >> 3, q = lin & 7;
            *(uint4*)(Bh + r * 72 + q * 8) =
                *(const uint4*)((const char*)g_Wth + ((size_t)r * DM + k0g) * 2 + q * 16);
            *(uint4*)(Bl + r * 72 + q * 8) =
                *(const uint4*)((const char*)g_Wtl + ((size_t)r * DM + k0g) * 2 + q * 16);
        }
        __syncthreads();
        #pragma unroll
        for (int ks = 0; ks < 4; ks++) {
            const int k0 = ks * 16;
            uint32_t a_h[2][4], a_l[2][4];
            #pragma unroll
            for (int mf = 0; mf < 2; mf++) {
                uint32_t off = (uint32_t)((wm * 32 + mf * 16 + (lane & 15)) * 72 +
                                          k0 + ((lane >> 4) << 3)) * 2;
                LDSM4(a_h[mf][0], a_h[mf][1], a_h[mf][2], a_h[mf][3], sAh + off);
                LDSM4(a_l[mf][0], a_l[mf][1], a_l[mf][2], a_l[mf][3], sAl + off);
            }
            uint32_t b_h[6][2], b_l[6][2];
            #pragma unroll
            for (int nb = 0; nb < 3; nb++) {
                uint32_t off = (uint32_t)((wn * 48 + nb * 16 + (lane & 7) + ((lane >> 4) << 3)) * 72 +
                                          k0 + (((lane >> 3) & 1) << 3)) * 2;
                LDSM4(b_h[2*nb][0], b_h[2*nb][1], b_h[2*nb+1][0], b_h[2*nb+1][1], sBh + off);
                LDSM4(b_l[2*nb][0], b_l[2*nb][1], b_l[2*nb+1][0], b_l[2*nb+1][1], sBl + off);
            }
            #pragma unroll
            for (int mf = 0; mf < 2; mf++)
                #pragma unroll
                for (int nf = 0; nf < 6; nf++) {
                    mma_bf16(acc[mf][nf], a_h[mf], b_h[nf]);
                    mma_bf16(acc[mf][nf], a_h[mf], b_l[nf]);
                    mma_bf16(acc[mf][nf], a_l[mf], b_h[nf]);
                }
        }
        __syncthreads();
    }

    __nv_bfloat16* sVh = Bh;
    __nv_bfloat16* sVl = Bl;
    #pragma unroll
    for (int mf = 0; mf < 2; mf++)
        #pragma unroll
        for (int nf = 0; nf < 6; nf++) {
            int gc = wn * 48 + nf * 8 + (lane & 3) * 2;
            int mt = gc >> 6, cm = gc & 63;
            int r0 = wm * 32 + mf * 16 + (lane >> 2);
            #pragma unroll
            for (int h = 0; h < 2; h++) {
                int rl = r0 + h * 8;
                float v0 = acc[mf][nf][h * 2 + 0], v1 = acc[mf][nf][h * 2 + 1];
                unsigned short h0, l0, h1, l1;
                if (mt < 2) {
                    const float* bias = mt ? bk : bq;
                    bsplit(v0 + bias[cm], h0, l0);
                    bsplit(v1 + bias[cm + 1], h1, l1);
                    size_t o = (size_t)(row0 + rl) * DH + cm;
                    *(uint32_t*)((mt ? g_Kh : g_Qh) + o) = pk2(h0, h1);
                    *(uint32_t*)((mt ? g_Kl : g_Ql) + o) = pk2(l0, l1);
                } else {
                    bsplit(v0 + bv[cm], h0, l0);
                    bsplit(v1 + bv[cm + 1], h1, l1);
                    sVh[cm * 136 + rl] = __ushort_as_bfloat16(h0);
                    sVh[(cm + 1) * 136 + rl] = __ushort_as_bfloat16(h1);
                    sVl[cm * 136 + rl] = __ushort_as_bfloat16(l0);
                    sVl[(cm + 1) * 136 + rl] = __ushort_as_bfloat16(l1);
                }
            }
        }
    __syncthreads();
    #pragma unroll
    for (int p = 0; p < 2; p++) {
        int lin = p * 512 + tid, r = lin >> 4, q = lin & 15;
        size_t dst = ((size_t)(bb * 64 + r) * SEQ + iloc + q * 8) * 2;
        *(uint4*)((char*)g_Vth + dst) = *(uint4*)(sVh + r * 136 + q * 8);
        *(uint4*)((char*)g_Vtl + dst) = *(uint4*)(sVl + r * 136 + q * 8);
    }
}

// ---------------- scores -> E = exp(S) (split) + column partial sums ----------------
// grid (16,16,8), block 256. smem: Qh,Ql,Kh,Kl [128][72] bf16; reused as Est f32 pitch 132.
__global__ __launch_bounds__(256) void scores_kernel() {
    extern __shared__ char smem[];
    const int tid = threadIdx.x, lane = tid & 31, w = tid >> 5;
    const int jt = blockIdx.x, it = blockIdx.y, bb = blockIdx.z;
    const int i0 = it * 128, j0 = jt * 128;

    __nv_bfloat16* T = (__nv_bfloat16*)smem;
    __nv_bfloat16* arr[4] = { T, T + 9216, T + 18432, T + 27648 };
    const __nv_bfloat16* src[4] = { g_Qh, g_Ql, g_Kh, g_Kl };
    #pragma unroll
    for (int a = 0; a < 4; a++) {
        const int rb = bb * SEQ + ((a < 2) ? i0 : j0);
        #pragma unroll
        for (int p = 0; p < 4; p++) {
            int lin = p * 256 + tid, r = lin >> 3, q = lin & 7;
            *(uint4*)(arr[a] + r * 72 + q * 8) =
                *(const uint4*)((const char*)src[a] + ((size_t)(rb + r) * DH) * 2 + q * 16);
        }
    }
    __syncthreads();

    const uint32_t sQh = s_u32(arr[0]), sQl = s_u32(arr[1]);
    const uint32_t sKh = s_u32(arr[2]), sKl = s_u32(arr[3]);
    const int wm = w & 1, wn = w >> 1;
    float acc[4][4][4];
    #pragma unroll
    for (int i = 0; i < 4; i++)
        #pragma unroll
        for (int j = 0; j < 4; j++)
            #pragma unroll
            for (int q = 0; q < 4; q++) acc[i][j][q] = 0.f;

    #pragma unroll
    for (int ks = 0; ks < 4; ks++) {
        const int k0 = ks * 16;
        uint32_t a_h[4][4], a_l[4][4];
        #pragma unroll
        for (int mf = 0; mf < 4; mf++) {
            uint32_t off = (uint32_t)((wm * 64 + mf * 16 + (lane & 15)) * 72 +
                                      k0 + ((lane >> 4) << 3)) * 2;
            LDSM4(a_h[mf][0], a_h[mf][1], a_h[mf][2], a_h[mf][3], sQh + off);
            LDSM4(a_l[mf][0], a_l[mf][1], a_l[mf][2], a_l[mf][3], sQl + off);
        }
        uint32_t b_h[4][2], b_l[4][2];
        #pragma unroll
        for (int nb = 0; nb < 2; nb++) {
            uint32_t off = (uint32_t)((wn * 32 + nb * 16 + (lane & 7) + ((lane >> 4) << 3)) * 72 +
                                      k0 + (((lane >> 3) & 1) << 3)) * 2;
            LDSM4(b_h[2*nb][0], b_h[2*nb][1], b_h[2*nb+1][0], b_h[2*nb+1][1], sKh + off);
            LDSM4(b_l[2*nb][0], b_l[2*nb][1], b_l[2*nb+1][0], b_l[2*nb+1][1], sKl + off);
        }
        #pragma unroll
        for (int mf = 0; mf < 4; mf++)
            #pragma unroll
            for (int nf = 0; nf < 4; nf++) {
                mma_bf16(acc[mf][nf], a_h[mf], b_h[nf]);
                mma_bf16(acc[mf][nf], a_h[mf], b_l[nf]);
                mma_bf16(acc[mf][nf], a_l[mf], b_h[nf]);
            }
    }
    __syncthreads();

    // stage E = exp(S/8) as f32 (pitch 132)
    float* Est = (float*)smem;
    #pragma unroll
    for (int mf = 0; mf < 4; mf++)
        #pragma unroll
        for (int nf = 0; nf < 4; nf++) {
            int col = wn * 32 + nf * 8 + (lane & 3) * 2;
            int r0 = wm * 64 + mf * 16 + (lane >> 2);
            #pragma unroll
            for (int h = 0; h < 2; h++) {
                Est[(r0 + h * 8) * 132 + col]     = __expf(0.125f * acc[mf][nf][h * 2 + 0]);
                Est[(r0 + h * 8) * 132 + col + 1] = __expf(0.125f * acc[mf][nf][h * 2 + 1]);
            }
        }
    __syncthreads();
    // split-store E to gmem (hi/lo bf16)
    #pragma unroll
    for (int p = 0; p < 16; p++) {
        int lin = p * 256 + tid, r = lin >> 5, c4 = lin & 31;
        float4 v = *(float4*)(Est + r * 132 + c4 * 4);
        unsigned short h0,l0,h1,l1,h2,l2,h3,l3;
        bsplit(v.x,h0,l0); bsplit(v.y,h1,l1); bsplit(v.z,h2,l2); bsplit(v.w,h3,l3);
        size_t base = (size_t)(bb * SEQ + i0 + r) * SEQ + j0 + c4 * 4;
        *(uint2*)(g_Eh + base) = make_uint2(pk2(h0,h1), pk2(h2,h3));
        *(uint2*)(g_El + base) = make_uint2(pk2(l0,l1), pk2(l2,l3));
    }
    // per-column partial sums (col = tid, threads 0..127)
    if (tid < 128) {
        float s = 0.f;
        #pragma unroll 8
        for (int i = 0; i < 128; i++) s += Est[i * 132 + tid];
        g_psum[(bb * ITILES + it) * SEQ + j0 + tid] = s;
    }
}

// ---------------- merge partial sums -> c_j = 1/sum ----------------
__global__ __launch_bounds__(256) void merge_stats_kernel() {
    int idx = blockIdx.x * 256 + threadIdx.x;
    int bb = idx >> 11, j = idx & 2047;
    float s = 0.f;
    #pragma unroll
    for (int it = 0; it < ITILES; it++)
        s += g_psum[(bb * ITILES + it) * SEQ + j];
    g_ci[idx] = 1.0f / s;
}

// ---------------- scale V' = diag(c) V in place ----------------
__global__ __launch_bounds__(256) void scale_v_kernel() {
    int idx = blockIdx.x * 256 + threadIdx.x;    // BATCH*DH*SEQ = 1M
    float v = __bfloat162float(g_Vth[idx]) + __bfloat162float(g_Vtl[idx]);
    float c = g_ci[(idx >> 17) * SEQ + (idx & 2047)];
    unsigned short h, l;
    bsplit(v * c, h, l);
    g_Vth[idx] = __ushort_as_bfloat16(h);
    g_Vtl[idx] = __ushort_as_bfloat16(l);
}

// ---------------- output: pure double-buffered GEMM O = E @ V' ----------------
// grid (16,8), block 256 (8 warps 4x2). C [128][64]; 32 j-chunks of 64.
// smem/buffer: Eh[128][72]@0, El@18432, Vh[64][72]@36864, Vl@46080 -> 55296 B; x2 = 110592
__global__ __launch_bounds__(256) void out_kernel(float* __restrict__ out) {
    extern __shared__ char smem[];
    const int tid = threadIdx.x, lane = tid & 31, w = tid >> 5;
    const int it = blockIdx.x, bb = blockIdx.y;
    const int i0 = it * 128;
    const uint32_t sbase = s_u32(smem);

    const int wm = w & 3, wn = w >> 2;
    float acc[2][4][4];
    #pragma unroll
    for (int i = 0; i < 2; i++)
        #pragma unroll
        for (int j = 0; j < 4; j++)
            #pragma unroll
            for (int q = 0; q < 4; q++) acc[i][j][q] = 0.f;

    const char* Ehg = (const char*)g_Eh;
    const char* Elg = (const char*)g_El;
    const char* Vhg = (const char*)g_Vth;
    const char* Vlg = (const char*)g_Vtl;

    // issue chunk c into buffer buf
    auto issue = [&](int c, int buf) {
        const uint32_t base = sbase + buf * 55296;
        const int j0 = c * 64;
        #pragma unroll
        for (int p = 0; p < 4; p++) {
            int lin = p * 256 + tid, r = lin >> 3, q = lin & 7;
            size_t srcb = ((size_t)(bb * SEQ + i0 + r) * SEQ + j0) * 2 + q * 16;
            uint32_t dst = base + (uint32_t)(r * 144 + q * 16);
            CPA16(dst, Ehg + srcb);
            CPA16(dst + 18432, Elg + srcb);
        }
        #pragma unroll
        for (int p = 0; p < 2; p++) {
            int lin = p * 256 + tid, r = lin >> 3, q = lin & 7;
            size_t srcb = ((size_t)(bb * 64 + r) * SEQ + j0) * 2 + q * 16;
            uint32_t dst = base + 36864 + (uint32_t)(r * 144 + q * 16);
            CPA16(dst, Vhg + srcb);
            CPA16(dst + 9216, Vlg + srcb);
        }
        CPA_COMMIT();
    };

    issue(0, 0);
    for (int c = 0; c < 32; c++) {
        if (c + 1 < 32) { issue(c + 1, (c + 1) & 1); CPA_WAIT1(); }
        else            { CPA_WAIT0(); }
        __syncthreads();

        const uint32_t base = sbase + (c & 1) * 55296;
        const uint32_t sE = base, sEl = base + 18432;
        const uint32_t sV = base + 36864, sVl = base + 46080;
        #pragma unroll
        for (int ks = 0; ks < 4; ks++) {
            const int k0 = ks * 16;
            uint32_t a_h[2][4], a_l[2][4];
            #pragma unroll
            for (int mf = 0; mf < 2; mf++) {
                uint32_t off = (uint32_t)((wm * 32 + mf * 16 + (lane & 15)) * 72 +
                                          k0 + ((lane >> 4) << 3)) * 2;
                LDSM4(a_h[mf][0], a_h[mf][1], a_h[mf][2], a_h[mf][3], sE + off);
                LDSM4(a_l[mf][0], a_l[mf][1], a_l[mf][2], a_l[mf][3], sEl + off);
            }
            uint32_t b_h[4][2], b_l[4][2];
            #pragma unroll
            for (int nb = 0; nb < 2; nb++) {
                uint32_t off = (uint32_t)((wn * 32 + nb * 16 + (lane & 7) + ((lane >> 4) << 3)) * 72 +
                                          k0 + (((lane >> 3) & 1) << 3)) * 2;
                LDSM4(b_h[2*nb][0], b_h[2*nb][1], b_h[2*nb+1][0], b_h[2*nb+1][1], sV + off);
                LDSM4(b_l[2*nb][0], b_l[2*nb][1], b_l[2*nb+1][0], b_l[2*nb+1][1], sVl + off);
            }
            #pragma unroll
            for (int mf = 0; mf < 2; mf++)
                #pragma unroll
                for (int nf = 0; nf < 4; nf++) {
                    mma_bf16(acc[mf][nf], a_h[mf], b_h[nf]);
                    mma_bf16(acc[mf][nf], a_h[mf], b_l[nf]);
                    mma_bf16(acc[mf][nf], a_l[mf], b_h[nf]);
                }
        }
        __syncthreads();
    }

    // epilogue: stage f32 (pitch 68) then coalesced store
    float* Ost = (float*)smem;
    #pragma unroll
    for (int mf = 0; mf < 2; mf++)
        #pragma unroll
        for (int nf = 0; nf < 4; nf++) {
            int col = wn * 32 + nf * 8 + (lane & 3) * 2;
            int r0 = wm * 32 + mf * 16 + (lane >> 2);
            #pragma unroll
            for (int h = 0; h < 2; h++) {
                Ost[(r0 + h * 8) * 68 + col]     = acc[mf][nf][h * 2 + 0];
                Ost[(r0 + h * 8) * 68 + col + 1] = acc[mf][nf][h * 2 + 1];
            }
        }
    __syncthreads();
    #pragma unroll
    for (int p = 0; p < 8; p++) {
        int lin = p * 256 + tid, r = lin >> 4, c4 = lin & 15;
        *(float4*)(out + ((size_t)(bb * SEQ + i0 + r)) * DH + c4 * 4) =
            *(float4*)(Ost + r * 68 + c4 * 4);
    }
}

// ---------------- launch ----------------
extern "C" void kernel_launch(void* const* d_in, const int* in_sizes, int n_in,
                              void* d_out, int out_size)
{
    const float* x  = (const float*)d_in[0];
    const float* Wq = (const float*)d_in[1];
    const float* bq = (const float*)d_in[2];
    const float* Wk = (const float*)d_in[3];
    const float* bk = (const float*)d_in[4];
    const float* Wv = (const float*)d_in[5];
    const float* bv = (const float*)d_in[6];
    float* out = (float*)d_out;

    cudaFuncSetAttribute(proj_kernel,   cudaFuncAttributeMaxDynamicSharedMemorySize, 92160);
    cudaFuncSetAttribute(scores_kernel, cudaFuncAttributeMaxDynamicSharedMemorySize, 73728);
    cudaFuncSetAttribute(out_kernel,    cudaFuncAttributeMaxDynamicSharedMemorySize, 110592);

    split_w_kernel<<<dim3(256, 3), 256>>>(Wq, Wk, Wv);
    proj_kernel<<<128, 512, 92160>>>(x, bq, bk, bv);
    scores_kernel<<<dim3(16, 16, 8), 256, 73728>>>();
    merge_stats_kernel<<<64, 256>>>();
    scale_v_kernel<<<BATCH * DH * SEQ / 256, 256>>>();
    out_kernel<<<dim3(16, 8), 256, 110592>>>(out);
}

// round 6
// speedup vs baseline: 3.3019x; 1.2295x over previous
#include <cuda_runtime.h>
#include <cuda_bf16.h>
#include <cuda_fp16.h>
#include <cstdint>

#define BATCH 8
#define SEQ   2048
#define DM    1024
#define DH    64
#define NTOK  (BATCH * SEQ)
#define ITILES 16

// ---------------- device scratch ----------------
__device__ __nv_bfloat16 g_Wth[3 * DH * DM];   // [mat*64+c][k]
__device__ __nv_bfloat16 g_Wtl[3 * DH * DM];
__device__ __nv_bfloat16 g_Qh[NTOK * DH], g_Ql[NTOK * DH];
__device__ __nv_bfloat16 g_Kh[NTOK * DH], g_Kl[NTOK * DH];
__device__ __nv_bfloat16 g_Vth[BATCH * DH * SEQ];  // [b][d][i]
__device__ __nv_bfloat16 g_Vtl[BATCH * DH * SEQ];
__device__ __half g_E[(size_t)NTOK * SEQ];         // exp(S) fp16, row-major [b,i,j]
__device__ __half g_Vf[BATCH * DH * SEQ];          // V' = diag(c) V, fp16, [b][d][i]
__device__ float g_psum[BATCH * ITILES * SEQ];
__device__ float g_ci[BATCH * SEQ];

// ---------------- helpers ----------------
__device__ __forceinline__ uint32_t s_u32(const void* p) {
    uint32_t a;
    asm("{ .reg .u64 t; cvta.to.shared.u64 t, %1; cvt.u32.u64 %0, t; }" : "=r"(a) : "l"(p));
    return a;
}
#define LDSM4(r0, r1, r2, r3, addr) \
    asm volatile("ldmatrix.sync.aligned.m8n8.x4.shared.b16 {%0,%1,%2,%3}, [%4];" \
                 : "=r"(r0), "=r"(r1), "=r"(r2), "=r"(r3) : "r"(addr))
#define CPA16(dst, src) \
    asm volatile("cp.async.cg.shared.global [%0], [%1], 16;" :: "r"(dst), "l"(src))
#define CPA_COMMIT() asm volatile("cp.async.commit_group;" ::: "memory")
#define CPA_WAIT1()  asm volatile("cp.async.wait_group 1;" ::: "memory")
#define CPA_WAIT0()  asm volatile("cp.async.wait_group 0;" ::: "memory")

__device__ __forceinline__ void mma_bf16(float* c, const uint32_t* a, const uint32_t* b) {
    asm volatile(
        "mma.sync.aligned.m16n8k16.row.col.f32.bf16.bf16.f32 "
        "{%0,%1,%2,%3}, {%4,%5,%6,%7}, {%8,%9}, {%0,%1,%2,%3};"
        : "+f"(c[0]), "+f"(c[1]), "+f"(c[2]), "+f"(c[3])
        : "r"(a[0]), "r"(a[1]), "r"(a[2]), "r"(a[3]), "r"(b[0]), "r"(b[1]));
}
__device__ __forceinline__ void mma_f16(float* c, const uint32_t* a, const uint32_t* b) {
    asm volatile(
        "mma.sync.aligned.m16n8k16.row.col.f32.f16.f16.f32 "
        "{%0,%1,%2,%3}, {%4,%5,%6,%7}, {%8,%9}, {%0,%1,%2,%3};"
        : "+f"(c[0]), "+f"(c[1]), "+f"(c[2]), "+f"(c[3])
        : "r"(a[0]), "r"(a[1]), "r"(a[2]), "r"(a[3]), "r"(b[0]), "r"(b[1]));
}

__device__ __forceinline__ void bsplit(float v, unsigned short& h, unsigned short& l) {
    __nv_bfloat16 bh = __float2bfloat16(v);
    __nv_bfloat16 bl = __float2bfloat16(v - __bfloat162float(bh));
    h = __bfloat16_as_ushort(bh); l = __bfloat16_as_ushort(bl);
}
__device__ __forceinline__ uint32_t pk2(unsigned short a, unsigned short b) {
    return (uint32_t)a | ((uint32_t)b << 16);
}

// ---------------- split/transpose W ----------------
__global__ __launch_bounds__(256) void split_w_kernel(
    const float* __restrict__ Wq, const float* __restrict__ Wk, const float* __restrict__ Wv) {
    int mt = blockIdx.y;
    const float* W = (mt == 0) ? Wq : (mt == 1) ? Wk : Wv;
    int idx = blockIdx.x * 256 + threadIdx.x;
    int k = idx >> 6, c = idx & 63;
    unsigned short h, l;
    bsplit(W[k * DH + c], h, l);
    g_Wth[(mt * 64 + c) * DM + k] = __ushort_as_bfloat16(h);
    g_Wtl[(mt * 64 + c) * DM + k] = __ushort_as_bfloat16(l);
}

// ---------------- fused QKV projection ----------------
__global__ __launch_bounds__(512) void proj_kernel(
    const float* __restrict__ x, const float* __restrict__ bq,
    const float* __restrict__ bk, const float* __restrict__ bv) {
    extern __shared__ char smem[];
    const int tid = threadIdx.x, lane = tid & 31, w = tid >> 5;
    const int row0 = blockIdx.x * 128;
    const int bb = row0 >> 11, iloc = row0 & 2047;

    __nv_bfloat16* Ah = (__nv_bfloat16*)smem;
    __nv_bfloat16* Al = Ah + 128 * 72;
    __nv_bfloat16* Bh = Al + 128 * 72;
    __nv_bfloat16* Bl = Bh + 192 * 72;
    const uint32_t sAh = s_u32(Ah), sAl = s_u32(Al), sBh = s_u32(Bh), sBl = s_u32(Bl);

    const int wm = w & 3, wn = w >> 2;
    float acc[2][6][4];
    #pragma unroll
    for (int i = 0; i < 2; i++)
        #pragma unroll
        for (int j = 0; j < 6; j++)
            #pragma unroll
            for (int q = 0; q < 4; q++) acc[i][j][q] = 0.f;

    for (int kc = 0; kc < 16; kc++) {
        const int k0g = kc * 64;
        {
            int r = tid >> 2, c0 = (tid & 3) * 16;
            const float4* src = (const float4*)(x + (size_t)(row0 + r) * DM + k0g + c0);
            unsigned short hs[16], ls[16];
            #pragma unroll
            for (int q = 0; q < 4; q++) {
                float4 v = src[q];
                bsplit(v.x, hs[q*4+0], ls[q*4+0]); bsplit(v.y, hs[q*4+1], ls[q*4+1]);
                bsplit(v.z, hs[q*4+2], ls[q*4+2]); bsplit(v.w, hs[q*4+3], ls[q*4+3]);
            }
            uint4* dh = (uint4*)(Ah + r * 72 + c0);
            uint4* dl = (uint4*)(Al + r * 72 + c0);
            dh[0] = make_uint4(pk2(hs[0],hs[1]), pk2(hs[2],hs[3]), pk2(hs[4],hs[5]), pk2(hs[6],hs[7]));
            dh[1] = make_uint4(pk2(hs[8],hs[9]), pk2(hs[10],hs[11]), pk2(hs[12],hs[13]), pk2(hs[14],hs[15]));
            dl[0] = make_uint4(pk2(ls[0],ls[1]), pk2(ls[2],ls[3]), pk2(ls[4],ls[5]), pk2(ls[6],ls[7]));
            dl[1] = make_uint4(pk2(ls[8],ls[9]), pk2(ls[10],ls[11]), pk2(ls[12],ls[13]), pk2(ls[14],ls[15]));
        }
        #pragma unroll
        for (int p = 0; p < 3; p++) {
            int lin = p * 512 + tid, r = lin >> 3, q = lin & 7;
            *(uint4*)(Bh + r * 72 + q * 8) =
                *(const uint4*)((const char*)g_Wth + ((size_t)r * DM + k0g) * 2 + q * 16);
            *(uint4*)(Bl + r * 72 + q * 8) =
                *(const uint4*)((const char*)g_Wtl + ((size_t)r * DM + k0g) * 2 + q * 16);
        }
        __syncthreads();
        #pragma unroll
        for (int ks = 0; ks < 4; ks++) {
            const int k0 = ks * 16;
            uint32_t a_h[2][4], a_l[2][4];
            #pragma unroll
            for (int mf = 0; mf < 2; mf++) {
                uint32_t off = (uint32_t)((wm * 32 + mf * 16 + (lane & 15)) * 72 +
                                          k0 + ((lane >> 4) << 3)) * 2;
                LDSM4(a_h[mf][0], a_h[mf][1], a_h[mf][2], a_h[mf][3], sAh + off);
                LDSM4(a_l[mf][0], a_l[mf][1], a_l[mf][2], a_l[mf][3], sAl + off);
            }
            uint32_t b_h[6][2], b_l[6][2];
            #pragma unroll
            for (int nb = 0; nb < 3; nb++) {
                uint32_t off = (uint32_t)((wn * 48 + nb * 16 + (lane & 7) + ((lane >> 4) << 3)) * 72 +
                                          k0 + (((lane >> 3) & 1) << 3)) * 2;
                LDSM4(b_h[2*nb][0], b_h[2*nb][1], b_h[2*nb+1][0], b_h[2*nb+1][1], sBh + off);
                LDSM4(b_l[2*nb][0], b_l[2*nb][1], b_l[2*nb+1][0], b_l[2*nb+1][1], sBl + off);
            }
            #pragma unroll
            for (int mf = 0; mf < 2; mf++)
                #pragma unroll
                for (int nf = 0; nf < 6; nf++) {
                    mma_bf16(acc[mf][nf], a_h[mf], b_h[nf]);
                    mma_bf16(acc[mf][nf], a_h[mf], b_l[nf]);
                    mma_bf16(acc[mf][nf], a_l[mf], b_h[nf]);
                }
        }
        __syncthreads();
    }

    __nv_bfloat16* sVh = Bh;
    __nv_bfloat16* sVl = Bl;
    #pragma unroll
    for (int mf = 0; mf < 2; mf++)
        #pragma unroll
        for (int nf = 0; nf < 6; nf++) {
            int gc = wn * 48 + nf * 8 + (lane & 3) * 2;
            int mt = gc >> 6, cm = gc & 63;
            int r0 = wm * 32 + mf * 16 + (lane >> 2);
            #pragma unroll
            for (int h = 0; h < 2; h++) {
                int rl = r0 + h * 8;
                float v0 = acc[mf][nf][h * 2 + 0], v1 = acc[mf][nf][h * 2 + 1];
                unsigned short h0, l0, h1, l1;
                if (mt < 2) {
                    const float* bias = mt ? bk : bq;
                    bsplit(v0 + bias[cm], h0, l0);
                    bsplit(v1 + bias[cm + 1], h1, l1);
                    size_t o = (size_t)(row0 + rl) * DH + cm;
                    *(uint32_t*)((mt ? g_Kh : g_Qh) + o) = pk2(h0, h1);
                    *(uint32_t*)((mt ? g_Kl : g_Ql) + o) = pk2(l0, l1);
                } else {
                    bsplit(v0 + bv[cm], h0, l0);
                    bsplit(v1 + bv[cm + 1], h1, l1);
                    sVh[cm * 136 + rl] = __ushort_as_bfloat16(h0);
                    sVh[(cm + 1) * 136 + rl] = __ushort_as_bfloat16(h1);
                    sVl[cm * 136 + rl] = __ushort_as_bfloat16(l0);
                    sVl[(cm + 1) * 136 + rl] = __ushort_as_bfloat16(l1);
                }
            }
        }
    __syncthreads();
    #pragma unroll
    for (int p = 0; p < 2; p++) {
        int lin = p * 512 + tid, r = lin >> 4, q = lin & 15;
        size_t dst = ((size_t)(bb * 64 + r) * SEQ + iloc + q * 8) * 2;
        *(uint4*)((char*)g_Vth + dst) = *(uint4*)(sVh + r * 136 + q * 8);
        *(uint4*)((char*)g_Vtl + dst) = *(uint4*)(sVl + r * 136 + q * 8);
    }
}

// ---------------- scores -> E = exp(S) (fp16) + column partial sums ----------------
// grid (16,16,8), block 256. smem: Qh,Ql,Kh,Kl [128][72] bf16; reused as Est fp16 pitch 136.
__global__ __launch_bounds__(256) void scores_kernel() {
    extern __shared__ char smem[];
    const int tid = threadIdx.x, lane = tid & 31, w = tid >> 5;
    const int jt = blockIdx.x, it = blockIdx.y, bb = blockIdx.z;
    const int i0 = it * 128, j0 = jt * 128;

    __nv_bfloat16* T = (__nv_bfloat16*)smem;
    __nv_bfloat16* arr[4] = { T, T + 9216, T + 18432, T + 27648 };
    const __nv_bfloat16* src[4] = { g_Qh, g_Ql, g_Kh, g_Kl };
    #pragma unroll
    for (int a = 0; a < 4; a++) {
        const int rb = bb * SEQ + ((a < 2) ? i0 : j0);
        #pragma unroll
        for (int p = 0; p < 4; p++) {
            int lin = p * 256 + tid, r = lin >> 3, q = lin & 7;
            *(uint4*)(arr[a] + r * 72 + q * 8) =
                *(const uint4*)((const char*)src[a] + ((size_t)(rb + r) * DH) * 2 + q * 16);
        }
    }
    __syncthreads();

    const uint32_t sQh = s_u32(arr[0]), sQl = s_u32(arr[1]);
    const uint32_t sKh = s_u32(arr[2]), sKl = s_u32(arr[3]);
    const int wm = w & 1, wn = w >> 1;
    float acc[4][4][4];
    #pragma unroll
    for (int i = 0; i < 4; i++)
        #pragma unroll
        for (int j = 0; j < 4; j++)
            #pragma unroll
            for (int q = 0; q < 4; q++) acc[i][j][q] = 0.f;

    #pragma unroll
    for (int ks = 0; ks < 4; ks++) {
        const int k0 = ks * 16;
        uint32_t a_h[4][4], a_l[4][4];
        #pragma unroll
        for (int mf = 0; mf < 4; mf++) {
            uint32_t off = (uint32_t)((wm * 64 + mf * 16 + (lane & 15)) * 72 +
                                      k0 + ((lane >> 4) << 3)) * 2;
            LDSM4(a_h[mf][0], a_h[mf][1], a_h[mf][2], a_h[mf][3], sQh + off);
            LDSM4(a_l[mf][0], a_l[mf][1], a_l[mf][2], a_l[mf][3], sQl + off);
        }
        uint32_t b_h[4][2], b_l[4][2];
        #pragma unroll
        for (int nb = 0; nb < 2; nb++) {
            uint32_t off = (uint32_t)((wn * 32 + nb * 16 + (lane & 7) + ((lane >> 4) << 3)) * 72 +
                                      k0 + (((lane >> 3) & 1) << 3)) * 2;
            LDSM4(b_h[2*nb][0], b_h[2*nb][1], b_h[2*nb+1][0], b_h[2*nb+1][1], sKh + off);
            LDSM4(b_l[2*nb][0], b_l[2*nb][1], b_l[2*nb+1][0], b_l[2*nb+1][1], sKl + off);
        }
        #pragma unroll
        for (int mf = 0; mf < 4; mf++)
            #pragma unroll
            for (int nf = 0; nf < 4; nf++) {
                mma_bf16(acc[mf][nf], a_h[mf], b_h[nf]);
                mma_bf16(acc[mf][nf], a_h[mf], b_l[nf]);
                mma_bf16(acc[mf][nf], a_l[mf], b_h[nf]);
            }
    }
    __syncthreads();

    // stage E = exp(S/8) as fp16 (pitch 136 halves)
    __half* Est = (__half*)smem;
    #pragma unroll
    for (int mf = 0; mf < 4; mf++)
        #pragma unroll
        for (int nf = 0; nf < 4; nf++) {
            int col = wn * 32 + nf * 8 + (lane & 3) * 2;
            int r0 = wm * 64 + mf * 16 + (lane >> 2);
            #pragma unroll
            for (int h = 0; h < 2; h++) {
                float e0 = __expf(0.125f * acc[mf][nf][h * 2 + 0]);
                float e1 = __expf(0.125f * acc[mf][nf][h * 2 + 1]);
                *(__half2*)(Est + (r0 + h * 8) * 136 + col) = __floats2half2_rn(e0, e1);
            }
        }
    __syncthreads();
    // coalesced fp16 E store (128 rows x 256 B)
    #pragma unroll
    for (int p = 0; p < 8; p++) {
        int lin = p * 256 + tid, r = lin >> 4, c8 = lin & 15;
        *(uint4*)((char*)g_E + ((size_t)(bb * SEQ + i0 + r) * SEQ + j0) * 2 + c8 * 16) =
            *(uint4*)((char*)Est + r * 272 + c8 * 16);
    }
    // per-column partial sums from staged fp16 (self-consistent with stored E)
    if (tid < 128) {
        float s = 0.f;
        #pragma unroll 8
        for (int i = 0; i < 128; i++) s += __half2float(Est[i * 136 + tid]);
        g_psum[(bb * ITILES + it) * SEQ + j0 + tid] = s;
    }
}

// ---------------- merge partial sums -> c_j = 1/sum ----------------
__global__ __launch_bounds__(256) void merge_stats_kernel() {
    int idx = blockIdx.x * 256 + threadIdx.x;
    int bb = idx >> 11, j = idx & 2047;
    float s = 0.f;
    #pragma unroll
    for (int it = 0; it < ITILES; it++)
        s += g_psum[(bb * ITILES + it) * SEQ + j];
    g_ci[idx] = 1.0f / s;
}

// ---------------- V' = diag(c) V -> fp16 ----------------
__global__ __launch_bounds__(256) void scale_v_kernel() {
    int idx = blockIdx.x * 256 + threadIdx.x;    // BATCH*DH*SEQ = 1M; [b][d][i]
    float v = __bfloat162float(g_Vth[idx]) + __bfloat162float(g_Vtl[idx]);
    float c = g_ci[(idx >> 17) * SEQ + (idx & 2047)];
    g_Vf[idx] = __float2half(v * c);
}

// ---------------- output: double-buffered fp16 GEMM O = E @ V' ----------------
// grid (16,8), block 256 (8 warps 4x2). C [128][64]; 16 j-chunks of 128.
// per buffer: E [128][136]h @0 (34816 B), V [64][136]h @34816 (17408 B) -> 52224; x2 = 104448
__global__ __launch_bounds__(256) void out_kernel(float* __restrict__ out) {
    extern __shared__ char smem[];
    const int tid = threadIdx.x, lane = tid & 31, w = tid >> 5;
    const int it = blockIdx.x, bb = blockIdx.y;
    const int i0 = it * 128;
    const uint32_t sbase = s_u32(smem);

    const int wm = w & 3, wn = w >> 2;
    float acc[2][4][4];
    #pragma unroll
    for (int i = 0; i < 2; i++)
        #pragma unroll
        for (int j = 0; j < 4; j++)
            #pragma unroll
            for (int q = 0; q < 4; q++) acc[i][j][q] = 0.f;

    const char* Eg = (const char*)g_E;
    const char* Vg = (const char*)g_Vf;

    auto issue = [&](int c, int buf) {
        const uint32_t base = sbase + buf * 52224;
        const int j0 = c * 128;
        #pragma unroll
        for (int p = 0; p < 8; p++) {
            int lin = p * 256 + tid, r = lin >> 4, q = lin & 15;
            CPA16(base + (uint32_t)(r * 272 + q * 16),
                  Eg + ((size_t)(bb * SEQ + i0 + r) * SEQ + j0) * 2 + q * 16);
        }
        #pragma unroll
        for (int p = 0; p < 4; p++) {
            int lin = p * 256 + tid, r = lin >> 4, q = lin & 15;
            CPA16(base + 34816 + (uint32_t)(r * 272 + q * 16),
                  Vg + ((size_t)(bb * 64 + r) * SEQ + j0) * 2 + q * 16);
        }
        CPA_COMMIT();
    };

    issue(0, 0);
    for (int c = 0; c < 16; c++) {
        if (c + 1 < 16) { issue(c + 1, (c + 1) & 1); CPA_WAIT1(); }
        else            { CPA_WAIT0(); }
        __syncthreads();

        const uint32_t base = sbase + (c & 1) * 52224;
        const uint32_t sE = base, sV = base + 34816;
        #pragma unroll
        for (int ks = 0; ks < 8; ks++) {
            const int k0 = ks * 16;
            uint32_t a[2][4];
            #pragma unroll
            for (int mf = 0; mf < 2; mf++) {
                uint32_t off = (uint32_t)((wm * 32 + mf * 16 + (lane & 15)) * 136 +
                                          k0 + ((lane >> 4) << 3)) * 2;
                LDSM4(a[mf][0], a[mf][1], a[mf][2], a[mf][3], sE + off);
            }
            uint32_t b[4][2];
            #pragma unroll
            for (int nb = 0; nb < 2; nb++) {
                uint32_t off = (uint32_t)((wn * 32 + nb * 16 + (lane & 7) + ((lane >> 4) << 3)) * 136 +
                                          k0 + (((lane >> 3) & 1) << 3)) * 2;
                LDSM4(b[2*nb][0], b[2*nb][1], b[2*nb+1][0], b[2*nb+1][1], sV + off);
            }
            #pragma unroll
            for (int mf = 0; mf < 2; mf++)
                #pragma unroll
                for (int nf = 0; nf < 4; nf++)
                    mma_f16(acc[mf][nf], a[mf], b[nf]);
        }
        __syncthreads();
    }

    // epilogue: stage f32 (pitch 68) then coalesced store
    float* Ost = (float*)smem;
    #pragma unroll
    for (int mf = 0; mf < 2; mf++)
        #pragma unroll
        for (int nf = 0; nf < 4; nf++) {
            int col = wn * 32 + nf * 8 + (lane & 3) * 2;
            int r0 = wm * 32 + mf * 16 + (lane >> 2);
            #pragma unroll
            for (int h = 0; h < 2; h++) {
                Ost[(r0 + h * 8) * 68 + col]     = acc[mf][nf][h * 2 + 0];
                Ost[(r0 + h * 8) * 68 + col + 1] = acc[mf][nf][h * 2 + 1];
            }
        }
    __syncthreads();
    #pragma unroll
    for (int p = 0; p < 8; p++) {
        int lin = p * 256 + tid, r = lin >> 4, c4 = lin & 15;
        *(float4*)(out + ((size_t)(bb * SEQ + i0 + r)) * DH + c4 * 4) =
            *(float4*)(Ost + r * 68 + c4 * 4);
    }
}

// ---------------- launch ----------------
extern "C" void kernel_launch(void* const* d_in, const int* in_sizes, int n_in,
                              void* d_out, int out_size)
{
    const float* x  = (const float*)d_in[0];
    const float* Wq = (const float*)d_in[1];
    const float* bq = (const float*)d_in[2];
    const float* Wk = (const float*)d_in[3];
    const float* bk = (const float*)d_in[4];
    const float* Wv = (const float*)d_in[5];
    const float* bv = (const float*)d_in[6];
    float* out = (float*)d_out;

    cudaFuncSetAttribute(proj_kernel,   cudaFuncAttributeMaxDynamicSharedMemorySize, 92160);
    cudaFuncSetAttribute(scores_kernel, cudaFuncAttributeMaxDynamicSharedMemorySize, 73728);
    cudaFuncSetAttribute(out_kernel,    cudaFuncAttributeMaxDynamicSharedMemorySize, 104448);

    split_w_kernel<<<dim3(256, 3), 256>>>(Wq, Wk, Wv);
    proj_kernel<<<128, 512, 92160>>>(x, bq, bk, bv);
    scores_kernel<<<dim3(16, 16, 8), 256, 73728>>>();
    merge_stats_kernel<<<64, 256>>>();
    scale_v_kernel<<<BATCH * DH * SEQ / 256, 256>>>();
    out_kernel<<<dim3(16, 8), 256, 104448>>>(out);
}

// round 7
// speedup vs baseline: 3.6380x; 1.1018x over previous
#include <cuda_runtime.h>
#include <cuda_bf16.h>
#include <cuda_fp16.h>
#include <cstdint>

#define BATCH 8
#define SEQ   2048
#define DM    1024
#define DH    64
#define NTOK  (BATCH * SEQ)
#define ITILES 16

// ---------------- device scratch ----------------
__device__ __nv_bfloat16 g_Wth[3 * DH * DM];   // [mat*64+c][k]
__device__ __nv_bfloat16 g_Wtl[3 * DH * DM];
__device__ __nv_bfloat16 g_Qh[NTOK * DH], g_Ql[NTOK * DH];
__device__ __nv_bfloat16 g_Kh[NTOK * DH], g_Kl[NTOK * DH];
__device__ __nv_bfloat16 g_Vth[BATCH * DH * SEQ];  // [b][d][i]
__device__ __nv_bfloat16 g_Vtl[BATCH * DH * SEQ];
__device__ __half g_E[(size_t)NTOK * SEQ];         // exp(S) fp16, [b,i,j]
__device__ __half g_Vf[BATCH * DH * SEQ];          // V' = diag(c) V, fp16, [b][d][i]
__device__ float g_psum[BATCH * ITILES * SEQ];
__device__ float g_ci[BATCH * SEQ];

// ---------------- helpers ----------------
__device__ __forceinline__ uint32_t s_u32(const void* p) {
    uint32_t a;
    asm("{ .reg .u64 t; cvta.to.shared.u64 t, %1; cvt.u32.u64 %0, t; }" : "=r"(a) : "l"(p));
    return a;
}
#define LDSM4(r0, r1, r2, r3, addr) \
    asm volatile("ldmatrix.sync.aligned.m8n8.x4.shared.b16 {%0,%1,%2,%3}, [%4];" \
                 : "=r"(r0), "=r"(r1), "=r"(r2), "=r"(r3) : "r"(addr))
#define CPA16(dst, src) \
    asm volatile("cp.async.cg.shared.global [%0], [%1], 16;" :: "r"(dst), "l"(src))
#define CPA_COMMIT() asm volatile("cp.async.commit_group;" ::: "memory")
#define CPA_WAIT1()  asm volatile("cp.async.wait_group 1;" ::: "memory")
#define CPA_WAIT0()  asm volatile("cp.async.wait_group 0;" ::: "memory")

__device__ __forceinline__ void mma_bf16(float* c, const uint32_t* a, const uint32_t* b) {
    asm volatile(
        "mma.sync.aligned.m16n8k16.row.col.f32.bf16.bf16.f32 "
        "{%0,%1,%2,%3}, {%4,%5,%6,%7}, {%8,%9}, {%0,%1,%2,%3};"
        : "+f"(c[0]), "+f"(c[1]), "+f"(c[2]), "+f"(c[3])
        : "r"(a[0]), "r"(a[1]), "r"(a[2]), "r"(a[3]), "r"(b[0]), "r"(b[1]));
}
__device__ __forceinline__ void mma_f16(float* c, const uint32_t* a, const uint32_t* b) {
    asm volatile(
        "mma.sync.aligned.m16n8k16.row.col.f32.f16.f16.f32 "
        "{%0,%1,%2,%3}, {%4,%5,%6,%7}, {%8,%9}, {%0,%1,%2,%3};"
        : "+f"(c[0]), "+f"(c[1]), "+f"(c[2]), "+f"(c[3])
        : "r"(a[0]), "r"(a[1]), "r"(a[2]), "r"(a[3]), "r"(b[0]), "r"(b[1]));
}

__device__ __forceinline__ void bsplit(float v, unsigned short& h, unsigned short& l) {
    __nv_bfloat16 bh = __float2bfloat16(v);
    __nv_bfloat16 bl = __float2bfloat16(v - __bfloat162float(bh));
    h = __bfloat16_as_ushort(bh); l = __bfloat16_as_ushort(bl);
}
__device__ __forceinline__ uint32_t pk2(unsigned short a, unsigned short b) {
    return (uint32_t)a | ((uint32_t)b << 16);
}

// ---------------- split/transpose W ----------------
__global__ __launch_bounds__(256) void split_w_kernel(
    const float* __restrict__ Wq, const float* __restrict__ Wk, const float* __restrict__ Wv) {
    int mt = blockIdx.y;
    const float* W = (mt == 0) ? Wq : (mt == 1) ? Wk : Wv;
    int idx = blockIdx.x * 256 + threadIdx.x;
    int k = idx >> 6, c = idx & 63;
    unsigned short h, l;
    bsplit(W[k * DH + c], h, l);
    g_Wth[(mt * 64 + c) * DM + k] = __ushort_as_bfloat16(h);
    g_Wtl[(mt * 64 + c) * DM + k] = __ushort_as_bfloat16(l);
}

// ---------------- fused QKV projection: 2-stage pipelined ----------------
// grid 128, block 512. Stage layout (92160 B each, x2):
//   Ah @0 (18432), Al @18432, Bh @36864 (27648), Bl @64512
__global__ __launch_bounds__(512) void proj_kernel(
    const float* __restrict__ x, const float* __restrict__ bq,
    const float* __restrict__ bk, const float* __restrict__ bv) {
    extern __shared__ char smem[];
    const uint32_t sbase = s_u32(smem);
    const int tid = threadIdx.x, lane = tid & 31, w = tid >> 5;
    const int row0 = blockIdx.x * 128;
    const int bb = row0 >> 11, iloc = row0 & 2047;

    const int wm = w & 3, wn = w >> 2;
    float acc[2][6][4];
    #pragma unroll
    for (int i = 0; i < 2; i++)
        #pragma unroll
        for (int j = 0; j < 6; j++)
            #pragma unroll
            for (int q = 0; q < 4; q++) acc[i][j][q] = 0.f;

    const int xr_r = tid >> 2, xr_c = (tid & 3) * 16;

    auto ldx = [&](int kc, float4* xr) {
        const float4* src = (const float4*)(x + (size_t)(row0 + xr_r) * DM + kc * 64 + xr_c);
        xr[0] = src[0]; xr[1] = src[1]; xr[2] = src[2]; xr[3] = src[3];
    };
    auto splitA = [&](const float4* xr, int st) {
        __nv_bfloat16* Ah = (__nv_bfloat16*)(smem + st * 92160);
        __nv_bfloat16* Al = (__nv_bfloat16*)(smem + st * 92160 + 18432);
        unsigned short hs[16], ls[16];
        #pragma unroll
        for (int q = 0; q < 4; q++) {
            float4 v = xr[q];
            bsplit(v.x, hs[q*4+0], ls[q*4+0]); bsplit(v.y, hs[q*4+1], ls[q*4+1]);
            bsplit(v.z, hs[q*4+2], ls[q*4+2]); bsplit(v.w, hs[q*4+3], ls[q*4+3]);
        }
        uint4* dh = (uint4*)(Ah + xr_r * 72 + xr_c);
        uint4* dl = (uint4*)(Al + xr_r * 72 + xr_c);
        dh[0] = make_uint4(pk2(hs[0],hs[1]), pk2(hs[2],hs[3]), pk2(hs[4],hs[5]), pk2(hs[6],hs[7]));
        dh[1] = make_uint4(pk2(hs[8],hs[9]), pk2(hs[10],hs[11]), pk2(hs[12],hs[13]), pk2(hs[14],hs[15]));
        dl[0] = make_uint4(pk2(ls[0],ls[1]), pk2(ls[2],ls[3]), pk2(ls[4],ls[5]), pk2(ls[6],ls[7]));
        dl[1] = make_uint4(pk2(ls[8],ls[9]), pk2(ls[10],ls[11]), pk2(ls[12],ls[13]), pk2(ls[14],ls[15]));
    };
    auto ldW = [&](int kc, int st) {
        uint32_t bh = sbase + st * 92160 + 36864;
        uint32_t bl = sbase + st * 92160 + 64512;
        #pragma unroll
        for (int p = 0; p < 3; p++) {
            int lin = p * 512 + tid, r = lin >> 3, q = lin & 7;
            CPA16(bh + (uint32_t)(r * 144 + q * 16),
                  (const char*)g_Wth + ((size_t)r * DM + kc * 64) * 2 + q * 16);
            CPA16(bl + (uint32_t)(r * 144 + q * 16),
                  (const char*)g_Wtl + ((size_t)r * DM + kc * 64) * 2 + q * 16);
        }
        CPA_COMMIT();
    };

    float4 xr[4];
    ldx(0, xr);
    ldW(0, 0);
    splitA(xr, 0);
    CPA_WAIT0();
    __syncthreads();

    for (int c = 0; c < 16; c++) {
        const int cur = c & 1;
        if (c < 15) { ldx(c + 1, xr); ldW(c + 1, cur ^ 1); }

        const uint32_t S = sbase + cur * 92160;
        const uint32_t sAh = S, sAl = S + 18432, sBh = S + 36864, sBl = S + 64512;
        #pragma unroll
        for (int ks = 0; ks < 4; ks++) {
            const int k0 = ks * 16;
            uint32_t a_h[2][4], a_l[2][4];
            #pragma unroll
            for (int mf = 0; mf < 2; mf++) {
                uint32_t off = (uint32_t)((wm * 32 + mf * 16 + (lane & 15)) * 72 +
                                          k0 + ((lane >> 4) << 3)) * 2;
                LDSM4(a_h[mf][0], a_h[mf][1], a_h[mf][2], a_h[mf][3], sAh + off);
                LDSM4(a_l[mf][0], a_l[mf][1], a_l[mf][2], a_l[mf][3], sAl + off);
            }
            uint32_t b_h[6][2], b_l[6][2];
            #pragma unroll
            for (int nb = 0; nb < 3; nb++) {
                uint32_t off = (uint32_t)((wn * 48 + nb * 16 + (lane & 7) + ((lane >> 4) << 3)) * 72 +
                                          k0 + (((lane >> 3) & 1) << 3)) * 2;
                LDSM4(b_h[2*nb][0], b_h[2*nb][1], b_h[2*nb+1][0], b_h[2*nb+1][1], sBh + off);
                LDSM4(b_l[2*nb][0], b_l[2*nb][1], b_l[2*nb+1][0], b_l[2*nb+1][1], sBl + off);
            }
            #pragma unroll
            for (int mf = 0; mf < 2; mf++)
                #pragma unroll
                for (int nf = 0; nf < 6; nf++) {
                    mma_bf16(acc[mf][nf], a_h[mf], b_h[nf]);
                    mma_bf16(acc[mf][nf], a_h[mf], b_l[nf]);
                    mma_bf16(acc[mf][nf], a_l[mf], b_h[nf]);
                }
        }
        if (c < 15) { splitA(xr, cur ^ 1); CPA_WAIT0(); }
        __syncthreads();
    }

    // epilogue: Q/K direct split stores; V staged transposed in stage-0 B region
    __nv_bfloat16* sVh = (__nv_bfloat16*)(smem + 36864);
    __nv_bfloat16* sVl = (__nv_bfloat16*)(smem + 64512);
    #pragma unroll
    for (int mf = 0; mf < 2; mf++)
        #pragma unroll
        for (int nf = 0; nf < 6; nf++) {
            int gc = wn * 48 + nf * 8 + (lane & 3) * 2;
            int mt = gc >> 6, cm = gc & 63;
            int r0 = wm * 32 + mf * 16 + (lane >> 2);
            #pragma unroll
            for (int h = 0; h < 2; h++) {
                int rl = r0 + h * 8;
                float v0 = acc[mf][nf][h * 2 + 0], v1 = acc[mf][nf][h * 2 + 1];
                unsigned short h0, l0, h1, l1;
                if (mt < 2) {
                    const float* bias = mt ? bk : bq;
                    bsplit(v0 + bias[cm], h0, l0);
                    bsplit(v1 + bias[cm + 1], h1, l1);
                    size_t o = (size_t)(row0 + rl) * DH + cm;
                    *(uint32_t*)((mt ? g_Kh : g_Qh) + o) = pk2(h0, h1);
                    *(uint32_t*)((mt ? g_Kl : g_Ql) + o) = pk2(l0, l1);
                } else {
                    bsplit(v0 + bv[cm], h0, l0);
                    bsplit(v1 + bv[cm + 1], h1, l1);
                    sVh[cm * 136 + rl] = __ushort_as_bfloat16(h0);
                    sVh[(cm + 1) * 136 + rl] = __ushort_as_bfloat16(h1);
                    sVl[cm * 136 + rl] = __ushort_as_bfloat16(l0);
                    sVl[(cm + 1) * 136 + rl] = __ushort_as_bfloat16(l1);
                }
            }
        }
    __syncthreads();
    #pragma unroll
    for (int p = 0; p < 2; p++) {
        int lin = p * 512 + tid, r = lin >> 4, q = lin & 15;
        size_t dst = ((size_t)(bb * 64 + r) * SEQ + iloc + q * 8) * 2;
        *(uint4*)((char*)g_Vth + dst) = *(uint4*)(sVh + r * 136 + q * 8);
        *(uint4*)((char*)g_Vtl + dst) = *(uint4*)(sVl + r * 136 + q * 8);
    }
}

// ---------------- scores -> E = exp(S) (fp16) + column partial sums ----------------
__global__ __launch_bounds__(256) void scores_kernel() {
    extern __shared__ char smem[];
    __shared__ float sred[256];
    const int tid = threadIdx.x, lane = tid & 31, w = tid >> 5;
    const int jt = blockIdx.x, it = blockIdx.y, bb = blockIdx.z;
    const int i0 = it * 128, j0 = jt * 128;

    __nv_bfloat16* T = (__nv_bfloat16*)smem;
    __nv_bfloat16* arr[4] = { T, T + 9216, T + 18432, T + 27648 };
    const __nv_bfloat16* src[4] = { g_Qh, g_Ql, g_Kh, g_Kl };
    #pragma unroll
    for (int a = 0; a < 4; a++) {
        const int rb = bb * SEQ + ((a < 2) ? i0 : j0);
        #pragma unroll
        for (int p = 0; p < 4; p++) {
            int lin = p * 256 + tid, r = lin >> 3, q = lin & 7;
            *(uint4*)(arr[a] + r * 72 + q * 8) =
                *(const uint4*)((const char*)src[a] + ((size_t)(rb + r) * DH) * 2 + q * 16);
        }
    }
    __syncthreads();

    const uint32_t sQh = s_u32(arr[0]), sQl = s_u32(arr[1]);
    const uint32_t sKh = s_u32(arr[2]), sKl = s_u32(arr[3]);
    const int wm = w & 1, wn = w >> 1;
    float acc[4][4][4];
    #pragma unroll
    for (int i = 0; i < 4; i++)
        #pragma unroll
        for (int j = 0; j < 4; j++)
            #pragma unroll
            for (int q = 0; q < 4; q++) acc[i][j][q] = 0.f;

    #pragma unroll
    for (int ks = 0; ks < 4; ks++) {
        const int k0 = ks * 16;
        uint32_t a_h[4][4], a_l[4][4];
        #pragma unroll
        for (int mf = 0; mf < 4; mf++) {
            uint32_t off = (uint32_t)((wm * 64 + mf * 16 + (lane & 15)) * 72 +
                                      k0 + ((lane >> 4) << 3)) * 2;
            LDSM4(a_h[mf][0], a_h[mf][1], a_h[mf][2], a_h[mf][3], sQh + off);
            LDSM4(a_l[mf][0], a_l[mf][1], a_l[mf][2], a_l[mf][3], sQl + off);
        }
        uint32_t b_h[4][2], b_l[4][2];
        #pragma unroll
        for (int nb = 0; nb < 2; nb++) {
            uint32_t off = (uint32_t)((wn * 32 + nb * 16 + (lane & 7) + ((lane >> 4) << 3)) * 72 +
                                      k0 + (((lane >> 3) & 1) << 3)) * 2;
            LDSM4(b_h[2*nb][0], b_h[2*nb][1], b_h[2*nb+1][0], b_h[2*nb+1][1], sKh + off);
            LDSM4(b_l[2*nb][0], b_l[2*nb][1], b_l[2*nb+1][0], b_l[2*nb+1][1], sKl + off);
        }
        #pragma unroll
        for (int mf = 0; mf < 4; mf++)
            #pragma unroll
            for (int nf = 0; nf < 4; nf++) {
                mma_bf16(acc[mf][nf], a_h[mf], b_h[nf]);
                mma_bf16(acc[mf][nf], a_h[mf], b_l[nf]);
                mma_bf16(acc[mf][nf], a_l[mf], b_h[nf]);
            }
    }
    __syncthreads();

    // stage E = exp(S/8) as fp16 (pitch 136 halves)
    __half* Est = (__half*)smem;
    #pragma unroll
    for (int mf = 0; mf < 4; mf++)
        #pragma unroll
        for (int nf = 0; nf < 4; nf++) {
            int col = wn * 32 + nf * 8 + (lane & 3) * 2;
            int r0 = wm * 64 + mf * 16 + (lane >> 2);
            #pragma unroll
            for (int h = 0; h < 2; h++) {
                float e0 = __expf(0.125f * acc[mf][nf][h * 2 + 0]);
                float e1 = __expf(0.125f * acc[mf][nf][h * 2 + 1]);
                *(__half2*)(Est + (r0 + h * 8) * 136 + col) = __floats2half2_rn(e0, e1);
            }
        }
    __syncthreads();
    // coalesced fp16 E store
    #pragma unroll
    for (int p = 0; p < 8; p++) {
        int lin = p * 256 + tid, r = lin >> 4, c8 = lin & 15;
        *(uint4*)((char*)g_E + ((size_t)(bb * SEQ + i0 + r) * SEQ + j0) * 2 + c8 * 16) =
            *(uint4*)((char*)Est + r * 272 + c8 * 16);
    }
    // per-column partial sums, all 256 threads (2-way split over rows)
    {
        int col = tid & 127, hf = tid >> 7;
        float s = 0.f;
        #pragma unroll 8
        for (int i = 0; i < 64; i++) s += __half2float(Est[(hf * 64 + i) * 136 + col]);
        sred[tid] = s;
        __syncthreads();
        if (tid < 128)
            g_psum[(bb * ITILES + it) * SEQ + j0 + tid] = sred[tid] + sred[tid + 128];
    }
}

// ---------------- merge partial sums -> c_j = 1/sum ----------------
__global__ __launch_bounds__(256) void merge_stats_kernel() {
    int idx = blockIdx.x * 256 + threadIdx.x;
    int bb = idx >> 11, j = idx & 2047;
    float s = 0.f;
    #pragma unroll
    for (int it = 0; it < ITILES; it++)
        s += g_psum[(bb * ITILES + it) * SEQ + j];
    g_ci[idx] = 1.0f / s;
}

// ---------------- V' = diag(c) V -> fp16 ----------------
__global__ __launch_bounds__(256) void scale_v_kernel() {
    int idx = blockIdx.x * 256 + threadIdx.x;
    float v = __bfloat162float(g_Vth[idx]) + __bfloat162float(g_Vtl[idx]);
    float c = g_ci[(idx >> 17) * SEQ + (idx & 2047)];
    g_Vf[idx] = __float2half(v * c);
}

// ---------------- output: double-buffered fp16 GEMM O = E @ V' ----------------
// grid (32,8), block 128 (4 warps 2x2). C [64][64]; 16 j-chunks of 128.
// per buffer: E [64][136]h @0 (17408 B), V [64][136]h @17408 -> 34816; x2 = 69632
__global__ __launch_bounds__(128) void out_kernel(float* __restrict__ out) {
    extern __shared__ char smem[];
    const int tid = threadIdx.x, lane = tid & 31, w = tid >> 5;
    const int it = blockIdx.x, bb = blockIdx.y;
    const int i0 = it * 64;
    const uint32_t sbase = s_u32(smem);

    const int wm = w & 1, wn = w >> 1;
    float acc[2][4][4];
    #pragma unroll
    for (int i = 0; i < 2; i++)
        #pragma unroll
        for (int j = 0; j < 4; j++)
            #pragma unroll
            for (int q = 0; q < 4; q++) acc[i][j][q] = 0.f;

    const char* Eg = (const char*)g_E;
    const char* Vg = (const char*)g_Vf;

    auto issue = [&](int c, int buf) {
        const uint32_t base = sbase + buf * 34816;
        const int j0 = c * 128;
        #pragma unroll
        for (int p = 0; p < 8; p++) {
            int lin = p * 128 + tid, r = lin >> 4, q = lin & 15;
            CPA16(base + (uint32_t)(r * 272 + q * 16),
                  Eg + ((size_t)(bb * SEQ + i0 + r) * SEQ + j0) * 2 + q * 16);
        }
        #pragma unroll
        for (int p = 0; p < 8; p++) {
            int lin = p * 128 + tid, r = lin >> 4, q = lin & 15;
            CPA16(base + 17408 + (uint32_t)(r * 272 + q * 16),
                  Vg + ((size_t)(bb * 64 + r) * SEQ + j0) * 2 + q * 16);
        }
        CPA_COMMIT();
    };

    issue(0, 0);
    for (int c = 0; c < 16; c++) {
        if (c + 1 < 16) { issue(c + 1, (c + 1) & 1); CPA_WAIT1(); }
        else            { CPA_WAIT0(); }
        __syncthreads();

        const uint32_t base = sbase + (c & 1) * 34816;
        const uint32_t sE = base, sV = base + 17408;
        #pragma unroll
        for (int ks = 0; ks < 8; ks++) {
            const int k0 = ks * 16;
            uint32_t a[2][4];
            #pragma unroll
            for (int mf = 0; mf < 2; mf++) {
                uint32_t off = (uint32_t)((wm * 32 + mf * 16 + (lane & 15)) * 136 +
                                          k0 + ((lane >> 4) << 3)) * 2;
                LDSM4(a[mf][0], a[mf][1], a[mf][2], a[mf][3], sE + off);
            }
            uint32_t b[4][2];
            #pragma unroll
            for (int nb = 0; nb < 2; nb++) {
                uint32_t off = (uint32_t)((wn * 32 + nb * 16 + (lane & 7) + ((lane >> 4) << 3)) * 136 +
                                          k0 + (((lane >> 3) & 1) << 3)) * 2;
                LDSM4(b[2*nb][0], b[2*nb][1], b[2*nb+1][0], b[2*nb+1][1], sV + off);
            }
            #pragma unroll
            for (int mf = 0; mf < 2; mf++)
                #pragma unroll
                for (int nf = 0; nf < 4; nf++)
                    mma_f16(acc[mf][nf], a[mf], b[nf]);
        }
        __syncthreads();
    }

    // epilogue: stage f32 (pitch 68) then coalesced store
    float* Ost = (float*)smem;
    #pragma unroll
    for (int mf = 0; mf < 2; mf++)
        #pragma unroll
        for (int nf = 0; nf < 4; nf++) {
            int col = wn * 32 + nf * 8 + (lane & 3) * 2;
            int r0 = wm * 32 + mf * 16 + (lane >> 2);
            #pragma unroll
            for (int h = 0; h < 2; h++) {
                Ost[(r0 + h * 8) * 68 + col]     = acc[mf][nf][h * 2 + 0];
                Ost[(r0 + h * 8) * 68 + col + 1] = acc[mf][nf][h * 2 + 1];
            }
        }
    __syncthreads();
    #pragma unroll
    for (int p = 0; p < 8; p++) {
        int lin = p * 128 + tid, r = lin >> 4, c4 = lin & 15;
        *(float4*)(out + ((size_t)(bb * SEQ + i0 + r)) * DH + c4 * 4) =
            *(float4*)(Ost + r * 68 + c4 * 4);
    }
}

// ---------------- launch ----------------
extern "C" void kernel_launch(void* const* d_in, const int* in_sizes, int n_in,
                              void* d_out, int out_size)
{
    const float* x  = (const float*)d_in[0];
    const float* Wq = (const float*)d_in[1];
    const float* bq = (const float*)d_in[2];
    const float* Wk = (const float*)d_in[3];
    const float* bk = (const float*)d_in[4];
    const float* Wv = (const float*)d_in[5];
    const float* bv = (const float*)d_in[6];
    float* out = (float*)d_out;

    cudaFuncSetAttribute(proj_kernel,   cudaFuncAttributeMaxDynamicSharedMemorySize, 184320);
    cudaFuncSetAttribute(scores_kernel, cudaFuncAttributeMaxDynamicSharedMemorySize, 73728);
    cudaFuncSetAttribute(out_kernel,    cudaFuncAttributeMaxDynamicSharedMemorySize, 69632);

    split_w_kernel<<<dim3(256, 3), 256>>>(Wq, Wk, Wv);
    proj_kernel<<<128, 512, 184320>>>(x, bq, bk, bv);
    scores_kernel<<<dim3(16, 16, 8), 256, 73728>>>();
    merge_stats_kernel<<<64, 256>>>();
    scale_v_kernel<<<BATCH * DH * SEQ / 256, 256>>>();
    out_kernel<<<dim3(32, 8), 128, 69632>>>(out);
}

// round 8
// speedup vs baseline: 4.3307x; 1.1904x over previous
#include <cuda_runtime.h>
#include <cuda_bf16.h>
#include <cuda_fp16.h>
#include <cstdint>

#define BATCH 8
#define SEQ   2048
#define DM    1024
#define DH    64
#define NTOK  (BATCH * SEQ)
#define ITILES 16

// ---------------- device scratch ----------------
__device__ __half g_W[3 * DH * DM];                // [mat*64+c][k], single fp16
__device__ __half g_Qh[NTOK * DH], g_Ql[NTOK * DH]; // Q fp16 hi/lo
__device__ __half g_K[NTOK * DH];                  // K single fp16
__device__ float  g_Vt[BATCH * DH * SEQ];          // V fp32, [b][d][i]
__device__ __half g_E[(size_t)NTOK * SEQ];         // exp(S) fp16, [b,i,j]
__device__ __half g_Vf[BATCH * DH * SEQ];          // V' = diag(c) V, fp16, [b][d][i]
__device__ float g_psum[BATCH * ITILES * SEQ];
__device__ float g_ci[BATCH * SEQ];

// ---------------- helpers ----------------
__device__ __forceinline__ uint32_t s_u32(const void* p) {
    uint32_t a;
    asm("{ .reg .u64 t; cvta.to.shared.u64 t, %1; cvt.u32.u64 %0, t; }" : "=r"(a) : "l"(p));
    return a;
}
#define LDSM4(r0, r1, r2, r3, addr) \
    asm volatile("ldmatrix.sync.aligned.m8n8.x4.shared.b16 {%0,%1,%2,%3}, [%4];" \
                 : "=r"(r0), "=r"(r1), "=r"(r2), "=r"(r3) : "r"(addr))
#define CPA16(dst, src) \
    asm volatile("cp.async.cg.shared.global [%0], [%1], 16;" :: "r"(dst), "l"(src))
#define CPA_COMMIT() asm volatile("cp.async.commit_group;" ::: "memory")
#define CPA_WAIT2()  asm volatile("cp.async.wait_group 2;" ::: "memory")
#define CPA_WAIT1()  asm volatile("cp.async.wait_group 1;" ::: "memory")
#define CPA_WAIT0()  asm volatile("cp.async.wait_group 0;" ::: "memory")

__device__ __forceinline__ void mma_f16(float* c, const uint32_t* a, const uint32_t* b) {
    asm volatile(
        "mma.sync.aligned.m16n8k16.row.col.f32.f16.f16.f32 "
        "{%0,%1,%2,%3}, {%4,%5,%6,%7}, {%8,%9}, {%0,%1,%2,%3};"
        : "+f"(c[0]), "+f"(c[1]), "+f"(c[2]), "+f"(c[3])
        : "r"(a[0]), "r"(a[1]), "r"(a[2]), "r"(a[3]), "r"(b[0]), "r"(b[1]));
}

__device__ __forceinline__ void hsplit(float v, unsigned short& h, unsigned short& l) {
    __half hh = __float2half(v);
    __half ll = __float2half(v - __half2float(hh));
    h = __half_as_ushort(hh); l = __half_as_ushort(ll);
}
__device__ __forceinline__ uint32_t pk2(unsigned short a, unsigned short b) {
    return (uint32_t)a | ((uint32_t)b << 16);
}

// ---------------- split/transpose W -> fp16 ----------------
__global__ __launch_bounds__(256) void split_w_kernel(
    const float* __restrict__ Wq, const float* __restrict__ Wk, const float* __restrict__ Wv) {
    int mt = blockIdx.y;
    const float* W = (mt == 0) ? Wq : (mt == 1) ? Wk : Wv;
    int idx = blockIdx.x * 256 + threadIdx.x;
    int k = idx >> 6, c = idx & 63;
    g_W[(mt * 64 + c) * DM + k] = __float2half(W[k * DH + c]);
}

// ---------------- fused QKV projection: 2-stage pipelined, fp16 2-term ----------------
// grid 128, block 512. Stage (64512 B x2): Ah @0 (18432), Al @18432, B @36864 (27648)
__global__ __launch_bounds__(512) void proj_kernel(
    const float* __restrict__ x, const float* __restrict__ bq,
    const float* __restrict__ bk, const float* __restrict__ bv) {
    extern __shared__ char smem[];
    const uint32_t sbase = s_u32(smem);
    const int tid = threadIdx.x, lane = tid & 31, w = tid >> 5;
    const int row0 = blockIdx.x * 128;
    const int bb = row0 >> 11, iloc = row0 & 2047;

    const int wm = w & 3, wn = w >> 2;          // rows wm*32, cols wn*48
    float acc[2][6][4];
    #pragma unroll
    for (int i = 0; i < 2; i++)
        #pragma unroll
        for (int j = 0; j < 6; j++)
            #pragma unroll
            for (int q = 0; q < 4; q++) acc[i][j][q] = 0.f;

    const int xr_r = tid >> 2, xr_c = (tid & 3) * 16;

    auto ldx = [&](int kc, float4* xr) {
        const float4* src = (const float4*)(x + (size_t)(row0 + xr_r) * DM + kc * 64 + xr_c);
        xr[0] = src[0]; xr[1] = src[1]; xr[2] = src[2]; xr[3] = src[3];
    };
    auto splitA = [&](const float4* xr, int st) {
        __half* Ah = (__half*)(smem + st * 64512);
        __half* Al = (__half*)(smem + st * 64512 + 18432);
        unsigned short hs[16], ls[16];
        #pragma unroll
        for (int q = 0; q < 4; q++) {
            float4 v = xr[q];
            hsplit(v.x, hs[q*4+0], ls[q*4+0]); hsplit(v.y, hs[q*4+1], ls[q*4+1]);
            hsplit(v.z, hs[q*4+2], ls[q*4+2]); hsplit(v.w, hs[q*4+3], ls[q*4+3]);
        }
        uint4* dh = (uint4*)(Ah + xr_r * 72 + xr_c);
        uint4* dl = (uint4*)(Al + xr_r * 72 + xr_c);
        dh[0] = make_uint4(pk2(hs[0],hs[1]), pk2(hs[2],hs[3]), pk2(hs[4],hs[5]), pk2(hs[6],hs[7]));
        dh[1] = make_uint4(pk2(hs[8],hs[9]), pk2(hs[10],hs[11]), pk2(hs[12],hs[13]), pk2(hs[14],hs[15]));
        dl[0] = make_uint4(pk2(ls[0],ls[1]), pk2(ls[2],ls[3]), pk2(ls[4],ls[5]), pk2(ls[6],ls[7]));
        dl[1] = make_uint4(pk2(ls[8],ls[9]), pk2(ls[10],ls[11]), pk2(ls[12],ls[13]), pk2(ls[14],ls[15]));
    };
    auto ldW = [&](int kc, int st) {
        uint32_t bw = sbase + st * 64512 + 36864;
        #pragma unroll
        for (int p = 0; p < 3; p++) {
            int lin = p * 512 + tid, r = lin >> 3, q = lin & 7;
            CPA16(bw + (uint32_t)(r * 144 + q * 16),
                  (const char*)g_W + ((size_t)r * DM + kc * 64) * 2 + q * 16);
        }
        CPA_COMMIT();
    };

    float4 xr[4];
    ldx(0, xr);
    ldW(0, 0);
    splitA(xr, 0);
    CPA_WAIT0();
    __syncthreads();

    for (int c = 0; c < 16; c++) {
        const int cur = c & 1;
        if (c < 15) { ldx(c + 1, xr); ldW(c + 1, cur ^ 1); }

        const uint32_t S = sbase + cur * 64512;
        const uint32_t sAh = S, sAl = S + 18432, sB = S + 36864;
        #pragma unroll
        for (int ks = 0; ks < 4; ks++) {
            const int k0 = ks * 16;
            uint32_t a_h[2][4], a_l[2][4];
            #pragma unroll
            for (int mf = 0; mf < 2; mf++) {
                uint32_t off = (uint32_t)((wm * 32 + mf * 16 + (lane & 15)) * 72 +
                                          k0 + ((lane >> 4) << 3)) * 2;
                LDSM4(a_h[mf][0], a_h[mf][1], a_h[mf][2], a_h[mf][3], sAh + off);
                LDSM4(a_l[mf][0], a_l[mf][1], a_l[mf][2], a_l[mf][3], sAl + off);
            }
            uint32_t b[6][2];
            #pragma unroll
            for (int nb = 0; nb < 3; nb++) {
                uint32_t off = (uint32_t)((wn * 48 + nb * 16 + (lane & 7) + ((lane >> 4) << 3)) * 72 +
                                          k0 + (((lane >> 3) & 1) << 3)) * 2;
                LDSM4(b[2*nb][0], b[2*nb][1], b[2*nb+1][0], b[2*nb+1][1], sB + off);
            }
            #pragma unroll
            for (int mf = 0; mf < 2; mf++)
                #pragma unroll
                for (int nf = 0; nf < 6; nf++) {
                    mma_f16(acc[mf][nf], a_h[mf], b[nf]);
                    mma_f16(acc[mf][nf], a_l[mf], b[nf]);
                }
        }
        if (c < 15) { splitA(xr, cur ^ 1); CPA_WAIT0(); }
        __syncthreads();
    }

    // epilogue: Q fp16 hi/lo, K single fp16 direct; V staged fp32 transposed
    float* sV = (float*)smem;     // [64][132] fp32 = 33792 B
    #pragma unroll
    for (int mf = 0; mf < 2; mf++)
        #pragma unroll
        for (int nf = 0; nf < 6; nf++) {
            int gc = wn * 48 + nf * 8 + (lane & 3) * 2;
            int mt = gc >> 6, cm = gc & 63;
            int r0 = wm * 32 + mf * 16 + (lane >> 2);
            #pragma unroll
            for (int h = 0; h < 2; h++) {
                int rl = r0 + h * 8;
                float v0 = acc[mf][nf][h * 2 + 0], v1 = acc[mf][nf][h * 2 + 1];
                if (mt == 0) {
                    unsigned short h0, l0, h1, l1;
                    hsplit(v0 + bq[cm], h0, l0);
                    hsplit(v1 + bq[cm + 1], h1, l1);
                    size_t o = (size_t)(row0 + rl) * DH + cm;
                    *(uint32_t*)(g_Qh + o) = pk2(h0, h1);
                    *(uint32_t*)(g_Ql + o) = pk2(l0, l1);
                } else if (mt == 1) {
                    __half k0v = __float2half(v0 + bk[cm]);
                    __half k1v = __float2half(v1 + bk[cm + 1]);
                    size_t o = (size_t)(row0 + rl) * DH + cm;
                    *(uint32_t*)(g_K + o) = pk2(__half_as_ushort(k0v), __half_as_ushort(k1v));
                } else {
                    sV[cm * 132 + rl]       = v0 + bv[cm];
                    sV[(cm + 1) * 132 + rl] = v1 + bv[cm + 1];
                }
            }
        }
    __syncthreads();
    #pragma unroll
    for (int p = 0; p < 4; p++) {
        int lin = p * 512 + tid, r = lin >> 5, q4 = lin & 31;   // 64 rows x 32 float4
        *(float4*)(g_Vt + (size_t)(bb * 64 + r) * SEQ + iloc + q4 * 4) =
            *(float4*)(sV + r * 132 + q4 * 4);
    }
}

// ---------------- scores -> E = exp(S) (fp16) + column partial sums ----------------
// grid (16,16,8), block 256. smem: Qh,Ql,K [128][72]h (55296 B); reused as Est fp16 pitch 136.
__global__ __launch_bounds__(256) void scores_kernel() {
    extern __shared__ char smem[];
    __shared__ float sred[256];
    const int tid = threadIdx.x, lane = tid & 31, w = tid >> 5;
    const int jt = blockIdx.x, it = blockIdx.y, bb = blockIdx.z;
    const int i0 = it * 128, j0 = jt * 128;
    const uint32_t sbase = s_u32(smem);

    {
        const __half* src[3] = { g_Qh, g_Ql, g_K };
        #pragma unroll
        for (int a = 0; a < 3; a++) {
            const int rb = bb * SEQ + ((a < 2) ? i0 : j0);
            #pragma unroll
            for (int p = 0; p < 4; p++) {
                int lin = p * 256 + tid, r = lin >> 3, q = lin & 7;
                CPA16(sbase + a * 18432 + (uint32_t)(r * 144 + q * 16),
                      (const char*)src[a] + ((size_t)(rb + r) * DH) * 2 + q * 16);
            }
        }
        CPA_COMMIT(); CPA_WAIT0();
    }
    __syncthreads();

    const uint32_t sQh = sbase, sQl = sbase + 18432, sK = sbase + 36864;
    const int wm = w & 1, wn = w >> 1;          // rows wm*64, cols wn*32
    float acc[4][4][4];
    #pragma unroll
    for (int i = 0; i < 4; i++)
        #pragma unroll
        for (int j = 0; j < 4; j++)
            #pragma unroll
            for (int q = 0; q < 4; q++) acc[i][j][q] = 0.f;

    #pragma unroll
    for (int ks = 0; ks < 4; ks++) {
        const int k0 = ks * 16;
        uint32_t a_h[4][4], a_l[4][4];
        #pragma unroll
        for (int mf = 0; mf < 4; mf++) {
            uint32_t off = (uint32_t)((wm * 64 + mf * 16 + (lane & 15)) * 72 +
                                      k0 + ((lane >> 4) << 3)) * 2;
            LDSM4(a_h[mf][0], a_h[mf][1], a_h[mf][2], a_h[mf][3], sQh + off);
            LDSM4(a_l[mf][0], a_l[mf][1], a_l[mf][2], a_l[mf][3], sQl + off);
        }
        uint32_t b[4][2];
        #pragma unroll
        for (int nb = 0; nb < 2; nb++) {
            uint32_t off = (uint32_t)((wn * 32 + nb * 16 + (lane & 7) + ((lane >> 4) << 3)) * 72 +
                                      k0 + (((lane >> 3) & 1) << 3)) * 2;
            LDSM4(b[2*nb][0], b[2*nb][1], b[2*nb+1][0], b[2*nb+1][1], sK + off);
        }
        #pragma unroll
        for (int mf = 0; mf < 4; mf++)
            #pragma unroll
            for (int nf = 0; nf < 4; nf++) {
                mma_f16(acc[mf][nf], a_h[mf], b[nf]);
                mma_f16(acc[mf][nf], a_l[mf], b[nf]);
            }
    }
    __syncthreads();

    // stage E = exp(S/8) as fp16 (pitch 136 halves)
    __half* Est = (__half*)smem;
    #pragma unroll
    for (int mf = 0; mf < 4; mf++)
        #pragma unroll
        for (int nf = 0; nf < 4; nf++) {
            int col = wn * 32 + nf * 8 + (lane & 3) * 2;
            int r0 = wm * 64 + mf * 16 + (lane >> 2);
            #pragma unroll
            for (int h = 0; h < 2; h++) {
                float e0 = __expf(0.125f * acc[mf][nf][h * 2 + 0]);
                float e1 = __expf(0.125f * acc[mf][nf][h * 2 + 1]);
                *(__half2*)(Est + (r0 + h * 8) * 136 + col) = __floats2half2_rn(e0, e1);
            }
        }
    __syncthreads();
    // coalesced fp16 E store
    #pragma unroll
    for (int p = 0; p < 8; p++) {
        int lin = p * 256 + tid, r = lin >> 4, c8 = lin & 15;
        *(uint4*)((char*)g_E + ((size_t)(bb * SEQ + i0 + r) * SEQ + j0) * 2 + c8 * 16) =
            *(uint4*)((char*)Est + r * 272 + c8 * 16);
    }
    // per-column partial sums (all 256 threads, 2-way row split)
    {
        int col = tid & 127, hf = tid >> 7;
        float s = 0.f;
        #pragma unroll 8
        for (int i = 0; i < 64; i++) s += __half2float(Est[(hf * 64 + i) * 136 + col]);
        sred[tid] = s;
        __syncthreads();
        if (tid < 128)
            g_psum[(bb * ITILES + it) * SEQ + j0 + tid] = sred[tid] + sred[tid + 128];
    }
}

// ---------------- merge partial sums -> c_j = 1/sum ----------------
__global__ __launch_bounds__(256) void merge_stats_kernel() {
    int idx = blockIdx.x * 256 + threadIdx.x;
    int bb = idx >> 11, j = idx & 2047;
    float s = 0.f;
    #pragma unroll
    for (int it = 0; it < ITILES; it++)
        s += g_psum[(bb * ITILES + it) * SEQ + j];
    g_ci[idx] = 1.0f / s;
}

// ---------------- V' = diag(c) V -> fp16 ----------------
__global__ __launch_bounds__(256) void scale_v_kernel() {
    int idx = blockIdx.x * 256 + threadIdx.x;      // [b][d][i]
    float v = g_Vt[idx];
    float c = g_ci[(idx >> 17) * SEQ + (idx & 2047)];
    g_Vf[idx] = __float2half(v * c);
}

// ---------------- output: 3-stage fp16 GEMM O = E @ V' ----------------
// grid (32,8), block 128 (4 warps 2x2). C [64][64]; 16 j-chunks of 128.
// per stage: E [64][136]h (17408 B) + V [64][136]h -> 34816; x3 = 104448
__global__ __launch_bounds__(128) void out_kernel(float* __restrict__ out) {
    extern __shared__ char smem[];
    const int tid = threadIdx.x, lane = tid & 31, w = tid >> 5;
    const int it = blockIdx.x, bb = blockIdx.y;
    const int i0 = it * 64;
    const uint32_t sbase = s_u32(smem);

    const int wm = w & 1, wn = w >> 1;
    float acc[2][4][4];
    #pragma unroll
    for (int i = 0; i < 2; i++)
        #pragma unroll
        for (int j = 0; j < 4; j++)
            #pragma unroll
            for (int q = 0; q < 4; q++) acc[i][j][q] = 0.f;

    const char* Eg = (const char*)g_E;
    const char* Vg = (const char*)g_Vf;

    auto issue = [&](int c) {
        const uint32_t base = sbase + (c % 3) * 34816;
        const int j0 = c * 128;
        #pragma unroll
        for (int p = 0; p < 8; p++) {
            int lin = p * 128 + tid, r = lin >> 4, q = lin & 15;
            CPA16(base + (uint32_t)(r * 272 + q * 16),
                  Eg + ((size_t)(bb * SEQ + i0 + r) * SEQ + j0) * 2 + q * 16);
        }
        #pragma unroll
        for (int p = 0; p < 8; p++) {
            int lin = p * 128 + tid, r = lin >> 4, q = lin & 15;
            CPA16(base + 17408 + (uint32_t)(r * 272 + q * 16),
                  Vg + ((size_t)(bb * 64 + r) * SEQ + j0) * 2 + q * 16);
        }
        CPA_COMMIT();
    };

    issue(0); issue(1);
    for (int c = 0; c < 16; c++) {
        if (c + 2 < 16) { issue(c + 2); CPA_WAIT2(); }
        else if (c + 1 < 16) { CPA_WAIT1(); }
        else { CPA_WAIT0(); }
        __syncthreads();

        const uint32_t base = sbase + (c % 3) * 34816;
        const uint32_t sE = base, sV = base + 17408;
        #pragma unroll
        for (int ks = 0; ks < 8; ks++) {
            const int k0 = ks * 16;
            uint32_t a[2][4];
            #pragma unroll
            for (int mf = 0; mf < 2; mf++) {
                uint32_t off = (uint32_t)((wm * 32 + mf * 16 + (lane & 15)) * 136 +
                                          k0 + ((lane >> 4) << 3)) * 2;
                LDSM4(a[mf][0], a[mf][1], a[mf][2], a[mf][3], sE + off);
            }
            uint32_t b[4][2];
            #pragma unroll
            for (int nb = 0; nb < 2; nb++) {
                uint32_t off = (uint32_t)((wn * 32 + nb * 16 + (lane & 7) + ((lane >> 4) << 3)) * 136 +
                                          k0 + (((lane >> 3) & 1) << 3)) * 2;
                LDSM4(b[2*nb][0], b[2*nb][1], b[2*nb+1][0], b[2*nb+1][1], sV + off);
            }
            #pragma unroll
            for (int mf = 0; mf < 2; mf++)
                #pragma unroll
                for (int nf = 0; nf < 4; nf++)
                    mma_f16(acc[mf][nf], a[mf], b[nf]);
        }
        __syncthreads();
    }

    // epilogue: stage f32 (pitch 68) then coalesced store
    float* Ost = (float*)smem;
    #pragma unroll
    for (int mf = 0; mf < 2; mf++)
        #pragma unroll
        for (int nf = 0; nf < 4; nf++) {
            int col = wn * 32 + nf * 8 + (lane & 3) * 2;
            int r0 = wm * 32 + mf * 16 + (lane >> 2);
            #pragma unroll
            for (int h = 0; h < 2; h++) {
                Ost[(r0 + h * 8) * 68 + col]     = acc[mf][nf][h * 2 + 0];
                Ost[(r0 + h * 8) * 68 + col + 1] = acc[mf][nf][h * 2 + 1];
            }
        }
    __syncthreads();
    #pragma unroll
    for (int p = 0; p < 8; p++) {
        int lin = p * 128 + tid, r = lin >> 4, c4 = lin & 15;
        *(float4*)(out + ((size_t)(bb * SEQ + i0 + r)) * DH + c4 * 4) =
            *(float4*)(Ost + r * 68 + c4 * 4);
    }
}

// ---------------- launch ----------------
extern "C" void kernel_launch(void* const* d_in, const int* in_sizes, int n_in,
                              void* d_out, int out_size)
{
    const float* x  = (const float*)d_in[0];
    const float* Wq = (const float*)d_in[1];
    const float* bq = (const float*)d_in[2];
    const float* Wk = (const float*)d_in[3];
    const float* bk = (const float*)d_in[4];
    const float* Wv = (const float*)d_in[5];
    const float* bv = (const float*)d_in[6];
    float* out = (float*)d_out;

    cudaFuncSetAttribute(proj_kernel,   cudaFuncAttributeMaxDynamicSharedMemorySize, 129024);
    cudaFuncSetAttribute(scores_kernel, cudaFuncAttributeMaxDynamicSharedMemorySize, 55296);
    cudaFuncSetAttribute(out_kernel,    cudaFuncAttributeMaxDynamicSharedMemorySize, 104448);

    split_w_kernel<<<dim3(256, 3), 256>>>(Wq, Wk, Wv);
    proj_kernel<<<128, 512, 129024>>>(x, bq, bk, bv);
    scores_kernel<<<dim3(16, 16, 8), 256, 55296>>>();
    merge_stats_kernel<<<64, 256>>>();
    scale_v_kernel<<<BATCH * DH * SEQ / 256, 256>>>();
    out_kernel<<<dim3(32, 8), 128, 104448>>>(out);
}

// round 9
// speedup vs baseline: 4.6937x; 1.0838x over previous
#include <cuda_runtime.h>
#include <cuda_bf16.h>
#include <cuda_fp16.h>
#include <cstdint>

#define BATCH 8
#define SEQ   2048
#define DM    1024
#define DH    64
#define NTOK  (BATCH * SEQ)
#define ITILES 16

// ---------------- device scratch ----------------
__device__ __half g_W[3 * DH * DM];                // [mat*64+c][k], fp16
__device__ __half g_Q[NTOK * DH];                  // Q fp16
__device__ __half g_K[NTOK * DH];                  // K fp16
__device__ float  g_Vt[BATCH * DH * SEQ];          // V fp32, [b][d][i]
__device__ __half g_E[(size_t)NTOK * SEQ];         // exp(S) fp16, [b,i,j]
__device__ __half g_Vf[BATCH * DH * SEQ];          // V' = diag(c) V, fp16, [b][d][i]
__device__ float g_psum[BATCH * ITILES * SEQ];

// ---------------- helpers ----------------
__device__ __forceinline__ uint32_t s_u32(const void* p) {
    uint32_t a;
    asm("{ .reg .u64 t; cvta.to.shared.u64 t, %1; cvt.u32.u64 %0, t; }" : "=r"(a) : "l"(p));
    return a;
}
#define LDSM4(r0, r1, r2, r3, addr) \
    asm volatile("ldmatrix.sync.aligned.m8n8.x4.shared.b16 {%0,%1,%2,%3}, [%4];" \
                 : "=r"(r0), "=r"(r1), "=r"(r2), "=r"(r3) : "r"(addr))
#define CPA16(dst, src) \
    asm volatile("cp.async.cg.shared.global [%0], [%1], 16;" :: "r"(dst), "l"(src))
#define CPA_COMMIT() asm volatile("cp.async.commit_group;" ::: "memory")
#define CPA_WAIT2()  asm volatile("cp.async.wait_group 2;" ::: "memory")
#define CPA_WAIT1()  asm volatile("cp.async.wait_group 1;" ::: "memory")
#define CPA_WAIT0()  asm volatile("cp.async.wait_group 0;" ::: "memory")

__device__ __forceinline__ void mma_f16(float* c, const uint32_t* a, const uint32_t* b) {
    asm volatile(
        "mma.sync.aligned.m16n8k16.row.col.f32.f16.f16.f32 "
        "{%0,%1,%2,%3}, {%4,%5,%6,%7}, {%8,%9}, {%0,%1,%2,%3};"
        : "+f"(c[0]), "+f"(c[1]), "+f"(c[2]), "+f"(c[3])
        : "r"(a[0]), "r"(a[1]), "r"(a[2]), "r"(a[3]), "r"(b[0]), "r"(b[1]));
}
__device__ __forceinline__ uint32_t pk2(unsigned short a, unsigned short b) {
    return (uint32_t)a | ((uint32_t)b << 16);
}
__device__ __forceinline__ unsigned short h16(float v) {
    return __half_as_ushort(__float2half(v));
}

// ---------------- W -> fp16 transpose ----------------
__global__ __launch_bounds__(256) void split_w_kernel(
    const float* __restrict__ Wq, const float* __restrict__ Wk, const float* __restrict__ Wv) {
    int mt = blockIdx.y;
    const float* W = (mt == 0) ? Wq : (mt == 1) ? Wk : Wv;
    int idx = blockIdx.x * 256 + threadIdx.x;
    int k = idx >> 6, c = idx & 63;
    g_W[(mt * 64 + c) * DM + k] = __float2half(W[k * DH + c]);
}

// ---------------- fused QKV projection: 2-stage, single-fp16 ----------------
// grid 128, block 512 (16 warps 4x4). Stage (46080 B x2): A @0 (18432), B @18432 (27648)
__global__ __launch_bounds__(512) void proj_kernel(
    const float* __restrict__ x, const float* __restrict__ bq,
    const float* __restrict__ bk, const float* __restrict__ bv) {
    extern __shared__ char smem[];
    const uint32_t sbase = s_u32(smem);
    const int tid = threadIdx.x, lane = tid & 31, w = tid >> 5;
    const int row0 = blockIdx.x * 128;
    const int bb = row0 >> 11, iloc = row0 & 2047;

    const int wm = w & 3, wn = w >> 2;          // rows wm*32, cols wn*48
    float acc[2][6][4];
    #pragma unroll
    for (int i = 0; i < 2; i++)
        #pragma unroll
        for (int j = 0; j < 6; j++)
            #pragma unroll
            for (int q = 0; q < 4; q++) acc[i][j][q] = 0.f;

    const int xr_r = tid >> 2, xr_c = (tid & 3) * 16;

    auto ldx = [&](int kc, float4* xr) {
        const float4* src = (const float4*)(x + (size_t)(row0 + xr_r) * DM + kc * 64 + xr_c);
        xr[0] = src[0]; xr[1] = src[1]; xr[2] = src[2]; xr[3] = src[3];
    };
    auto convA = [&](const float4* xr, int st) {
        __half* A = (__half*)(smem + st * 46080);
        unsigned short hs[16];
        #pragma unroll
        for (int q = 0; q < 4; q++) {
            float4 v = xr[q];
            hs[q*4+0] = h16(v.x); hs[q*4+1] = h16(v.y);
            hs[q*4+2] = h16(v.z); hs[q*4+3] = h16(v.w);
        }
        uint4* dh = (uint4*)(A + xr_r * 72 + xr_c);
        dh[0] = make_uint4(pk2(hs[0],hs[1]), pk2(hs[2],hs[3]), pk2(hs[4],hs[5]), pk2(hs[6],hs[7]));
        dh[1] = make_uint4(pk2(hs[8],hs[9]), pk2(hs[10],hs[11]), pk2(hs[12],hs[13]), pk2(hs[14],hs[15]));
    };
    auto ldW = [&](int kc, int st) {
        uint32_t bw = sbase + st * 46080 + 18432;
        #pragma unroll
        for (int p = 0; p < 3; p++) {
            int lin = p * 512 + tid, r = lin >> 3, q = lin & 7;
            CPA16(bw + (uint32_t)(r * 144 + q * 16),
                  (const char*)g_W + ((size_t)r * DM + kc * 64) * 2 + q * 16);
        }
        CPA_COMMIT();
    };

    float4 xr[4];
    ldx(0, xr);
    ldW(0, 0);
    convA(xr, 0);
    CPA_WAIT0();
    __syncthreads();

    for (int c = 0; c < 16; c++) {
        const int cur = c & 1;
        if (c < 15) { ldx(c + 1, xr); ldW(c + 1, cur ^ 1); }

        const uint32_t S = sbase + cur * 46080;
        const uint32_t sA = S, sB = S + 18432;
        #pragma unroll
        for (int ks = 0; ks < 4; ks++) {
            const int k0 = ks * 16;
            uint32_t a[2][4];
            #pragma unroll
            for (int mf = 0; mf < 2; mf++) {
                uint32_t off = (uint32_t)((wm * 32 + mf * 16 + (lane & 15)) * 72 +
                                          k0 + ((lane >> 4) << 3)) * 2;
                LDSM4(a[mf][0], a[mf][1], a[mf][2], a[mf][3], sA + off);
            }
            uint32_t b[6][2];
            #pragma unroll
            for (int nb = 0; nb < 3; nb++) {
                uint32_t off = (uint32_t)((wn * 48 + nb * 16 + (lane & 7) + ((lane >> 4) << 3)) * 72 +
                                          k0 + (((lane >> 3) & 1) << 3)) * 2;
                LDSM4(b[2*nb][0], b[2*nb][1], b[2*nb+1][0], b[2*nb+1][1], sB + off);
            }
            #pragma unroll
            for (int mf = 0; mf < 2; mf++)
                #pragma unroll
                for (int nf = 0; nf < 6; nf++)
                    mma_f16(acc[mf][nf], a[mf], b[nf]);
        }
        if (c < 15) { convA(xr, cur ^ 1); CPA_WAIT0(); }
        __syncthreads();
    }

    // epilogue: Q, K single fp16 direct; V staged fp32 transposed
    float* sV = (float*)smem;     // [64][132] fp32 = 33792 B
    #pragma unroll
    for (int mf = 0; mf < 2; mf++)
        #pragma unroll
        for (int nf = 0; nf < 6; nf++) {
            int gc = wn * 48 + nf * 8 + (lane & 3) * 2;
            int mt = gc >> 6, cm = gc & 63;
            int r0 = wm * 32 + mf * 16 + (lane >> 2);
            #pragma unroll
            for (int h = 0; h < 2; h++) {
                int rl = r0 + h * 8;
                float v0 = acc[mf][nf][h * 2 + 0], v1 = acc[mf][nf][h * 2 + 1];
                if (mt == 0) {
                    size_t o = (size_t)(row0 + rl) * DH + cm;
                    *(uint32_t*)(g_Q + o) = pk2(h16(v0 + bq[cm]), h16(v1 + bq[cm + 1]));
                } else if (mt == 1) {
                    size_t o = (size_t)(row0 + rl) * DH + cm;
                    *(uint32_t*)(g_K + o) = pk2(h16(v0 + bk[cm]), h16(v1 + bk[cm + 1]));
                } else {
                    sV[cm * 132 + rl]       = v0 + bv[cm];
                    sV[(cm + 1) * 132 + rl] = v1 + bv[cm + 1];
                }
            }
        }
    __syncthreads();
    #pragma unroll
    for (int p = 0; p < 4; p++) {
        int lin = p * 512 + tid, r = lin >> 5, q4 = lin & 31;
        *(float4*)(g_Vt + (size_t)(bb * 64 + r) * SEQ + iloc + q4 * 4) =
            *(float4*)(sV + r * 132 + q4 * 4);
    }
}

// ---------------- scores -> E = exp(S) (fp16) + column partial sums ----------------
// grid (16,16,8), block 256. smem: Q,K [128][72]h (36864 B); reused as Est fp16 pitch 136.
__global__ __launch_bounds__(256) void scores_kernel() {
    extern __shared__ char smem[];
    __shared__ float sred[256];
    const int tid = threadIdx.x, lane = tid & 31, w = tid >> 5;
    const int jt = blockIdx.x, it = blockIdx.y, bb = blockIdx.z;
    const int i0 = it * 128, j0 = jt * 128;
    const uint32_t sbase = s_u32(smem);

    {
        const __half* src[2] = { g_Q, g_K };
        #pragma unroll
        for (int a = 0; a < 2; a++) {
            const int rb = bb * SEQ + ((a == 0) ? i0 : j0);
            #pragma unroll
            for (int p = 0; p < 4; p++) {
                int lin = p * 256 + tid, r = lin >> 3, q = lin & 7;
                CPA16(sbase + a * 18432 + (uint32_t)(r * 144 + q * 16),
                      (const char*)src[a] + ((size_t)(rb + r) * DH) * 2 + q * 16);
            }
        }
        CPA_COMMIT(); CPA_WAIT0();
    }
    __syncthreads();

    const uint32_t sQ = sbase, sK = sbase + 18432;
    const int wm = w & 1, wn = w >> 1;          // rows wm*64, cols wn*32
    float acc[4][4][4];
    #pragma unroll
    for (int i = 0; i < 4; i++)
        #pragma unroll
        for (int j = 0; j < 4; j++)
            #pragma unroll
            for (int q = 0; q < 4; q++) acc[i][j][q] = 0.f;

    #pragma unroll
    for (int ks = 0; ks < 4; ks++) {
        const int k0 = ks * 16;
        uint32_t a[4][4];
        #pragma unroll
        for (int mf = 0; mf < 4; mf++) {
            uint32_t off = (uint32_t)((wm * 64 + mf * 16 + (lane & 15)) * 72 +
                                      k0 + ((lane >> 4) << 3)) * 2;
            LDSM4(a[mf][0], a[mf][1], a[mf][2], a[mf][3], sQ + off);
        }
        uint32_t b[4][2];
        #pragma unroll
        for (int nb = 0; nb < 2; nb++) {
            uint32_t off = (uint32_t)((wn * 32 + nb * 16 + (lane & 7) + ((lane >> 4) << 3)) * 72 +
                                      k0 + (((lane >> 3) & 1) << 3)) * 2;
            LDSM4(b[2*nb][0], b[2*nb][1], b[2*nb+1][0], b[2*nb+1][1], sK + off);
        }
        #pragma unroll
        for (int mf = 0; mf < 4; mf++)
            #pragma unroll
            for (int nf = 0; nf < 4; nf++)
                mma_f16(acc[mf][nf], a[mf], b[nf]);
    }
    __syncthreads();

    // stage E = exp(S/8) as fp16 (pitch 136 halves)
    __half* Est = (__half*)smem;
    #pragma unroll
    for (int mf = 0; mf < 4; mf++)
        #pragma unroll
        for (int nf = 0; nf < 4; nf++) {
            int col = wn * 32 + nf * 8 + (lane & 3) * 2;
            int r0 = wm * 64 + mf * 16 + (lane >> 2);
            #pragma unroll
            for (int h = 0; h < 2; h++) {
                float e0 = __expf(0.125f * acc[mf][nf][h * 2 + 0]);
                float e1 = __expf(0.125f * acc[mf][nf][h * 2 + 1]);
                *(__half2*)(Est + (r0 + h * 8) * 136 + col) = __floats2half2_rn(e0, e1);
            }
        }
    __syncthreads();
    // coalesced fp16 E store
    #pragma unroll
    for (int p = 0; p < 8; p++) {
        int lin = p * 256 + tid, r = lin >> 4, c8 = lin & 15;
        *(uint4*)((char*)g_E + ((size_t)(bb * SEQ + i0 + r) * SEQ + j0) * 2 + c8 * 16) =
            *(uint4*)((char*)Est + r * 272 + c8 * 16);
    }
    // per-column partial sums (all 256 threads, 2-way row split)
    {
        int col = tid & 127, hf = tid >> 7;
        float s = 0.f;
        #pragma unroll 8
        for (int i = 0; i < 64; i++) s += __half2float(Est[(hf * 64 + i) * 136 + col]);
        sred[tid] = s;
        __syncthreads();
        if (tid < 128)
            g_psum[(bb * ITILES + it) * SEQ + j0 + tid] = sred[tid] + sred[tid + 128];
    }
}

// ---------------- fused: merge psums -> c, then V' = c*V -> fp16 ----------------
// grid (16, 8), block 128. Thread owns column i = blockIdx.x*128+tid.
__global__ __launch_bounds__(128) void merge_scale_kernel() {
    const int bb = blockIdx.y;
    const int i = blockIdx.x * 128 + threadIdx.x;
    float s = 0.f;
    #pragma unroll
    for (int it = 0; it < ITILES; it++)
        s += g_psum[(bb * ITILES + it) * SEQ + i];
    const float c = 1.0f / s;
    #pragma unroll 8
    for (int d = 0; d < 64; d++) {
        size_t idx = (size_t)(bb * 64 + d) * SEQ + i;
        g_Vf[idx] = __float2half(g_Vt[idx] * c);
    }
}

// ---------------- output: 3-stage fp16 GEMM O = E @ V' ----------------
// grid (32,8), block 128 (4 warps 2x2). C [64][64]; 16 j-chunks of 128.
__global__ __launch_bounds__(128) void out_kernel(float* __restrict__ out) {
    extern __shared__ char smem[];
    const int tid = threadIdx.x, lane = tid & 31, w = tid >> 5;
    const int it = blockIdx.x, bb = blockIdx.y;
    const int i0 = it * 64;
    const uint32_t sbase = s_u32(smem);

    const int wm = w & 1, wn = w >> 1;
    float acc[2][4][4];
    #pragma unroll
    for (int i = 0; i < 2; i++)
        #pragma unroll
        for (int j = 0; j < 4; j++)
            #pragma unroll
            for (int q = 0; q < 4; q++) acc[i][j][q] = 0.f;

    const char* Eg = (const char*)g_E;
    const char* Vg = (const char*)g_Vf;

    auto issue = [&](int c) {
        const uint32_t base = sbase + (c % 3) * 34816;
        const int j0 = c * 128;
        #pragma unroll
        for (int p = 0; p < 8; p++) {
            int lin = p * 128 + tid, r = lin >> 4, q = lin & 15;
            CPA16(base + (uint32_t)(r * 272 + q * 16),
                  Eg + ((size_t)(bb * SEQ + i0 + r) * SEQ + j0) * 2 + q * 16);
        }
        #pragma unroll
        for (int p = 0; p < 8; p++) {
            int lin = p * 128 + tid, r = lin >> 4, q = lin & 15;
            CPA16(base + 17408 + (uint32_t)(r * 272 + q * 16),
                  Vg + ((size_t)(bb * 64 + r) * SEQ + j0) * 2 + q * 16);
        }
        CPA_COMMIT();
    };

    issue(0); issue(1);
    for (int c = 0; c < 16; c++) {
        if (c + 2 < 16) { issue(c + 2); CPA_WAIT2(); }
        else if (c + 1 < 16) { CPA_WAIT1(); }
        else { CPA_WAIT0(); }
        __syncthreads();

        const uint32_t base = sbase + (c % 3) * 34816;
        const uint32_t sE = base, sV = base + 17408;
        #pragma unroll
        for (int ks = 0; ks < 8; ks++) {
            const int k0 = ks * 16;
            uint32_t a[2][4];
            #pragma unroll
            for (int mf = 0; mf < 2; mf++) {
                uint32_t off = (uint32_t)((wm * 32 + mf * 16 + (lane & 15)) * 136 +
                                          k0 + ((lane >> 4) << 3)) * 2;
                LDSM4(a[mf][0], a[mf][1], a[mf][2], a[mf][3], sE + off);
            }
            uint32_t b[4][2];
            #pragma unroll
            for (int nb = 0; nb < 2; nb++) {
                uint32_t off = (uint32_t)((wn * 32 + nb * 16 + (lane & 7) + ((lane >> 4) << 3)) * 136 +
                                          k0 + (((lane >> 3) & 1) << 3)) * 2;
                LDSM4(b[2*nb][0], b[2*nb][1], b[2*nb+1][0], b[2*nb+1][1], sV + off);
            }
            #pragma unroll
            for (int mf = 0; mf < 2; mf++)
                #pragma unroll
                for (int nf = 0; nf < 4; nf++)
                    mma_f16(acc[mf][nf], a[mf], b[nf]);
        }
        __syncthreads();
    }

    // epilogue
    float* Ost = (float*)smem;
    #pragma unroll
    for (int mf = 0; mf < 2; mf++)
        #pragma unroll
        for (int nf = 0; nf < 4; nf++) {
            int col = wn * 32 + nf * 8 + (lane & 3) * 2;
            int r0 = wm * 32 + mf * 16 + (lane >> 2);
            #pragma unroll
            for (int h = 0; h < 2; h++) {
                Ost[(r0 + h * 8) * 68 + col]     = acc[mf][nf][h * 2 + 0];
                Ost[(r0 + h * 8) * 68 + col + 1] = acc[mf][nf][h * 2 + 1];
            }
        }
    __syncthreads();
    #pragma unroll
    for (int p = 0; p < 8; p++) {
        int lin = p * 128 + tid, r = lin >> 4, c4 = lin & 15;
        *(float4*)(out + ((size_t)(bb * SEQ + i0 + r)) * DH + c4 * 4) =
            *(float4*)(Ost + r * 68 + c4 * 4);
    }
}

// ---------------- launch ----------------
extern "C" void kernel_launch(void* const* d_in, const int* in_sizes, int n_in,
                              void* d_out, int out_size)
{
    const float* x  = (const float*)d_in[0];
    const float* Wq = (const float*)d_in[1];
    const float* bq = (const float*)d_in[2];
    const float* Wk = (const float*)d_in[3];
    const float* bk = (const float*)d_in[4];
    const float* Wv = (const float*)d_in[5];
    const float* bv = (const float*)d_in[6];
    float* out = (float*)d_out;

    cudaFuncSetAttribute(proj_kernel,   cudaFuncAttributeMaxDynamicSharedMemorySize, 92160);
    cudaFuncSetAttribute(scores_kernel, cudaFuncAttributeMaxDynamicSharedMemorySize, 36864);
    cudaFuncSetAttribute(out_kernel,    cudaFuncAttributeMaxDynamicSharedMemorySize, 104448);

    split_w_kernel<<<dim3(256, 3), 256>>>(Wq, Wk, Wv);
    proj_kernel<<<128, 512, 92160>>>(x, bq, bk, bv);
    scores_kernel<<<dim3(16, 16, 8), 256, 36864>>>();
    merge_scale_kernel<<<dim3(16, 8), 128>>>();
    out_kernel<<<dim3(32, 8), 128, 104448>>>(out);
}

// round 10
// speedup vs baseline: 5.2626x; 1.1212x over previous
#include <cuda_runtime.h>
#include <cuda_bf16.h>
#include <cuda_fp16.h>
#include <cstdint>

#define BATCH 8
#define SEQ   2048
#define DM    1024
#define DH    64
#define NTOK  (BATCH * SEQ)
#define ITILES 16

// ---------------- device scratch ----------------
__device__ __half g_W[3 * DH * DM];                // [mat*64+c][k], fp16
__device__ __half g_Q[NTOK * DH];                  // Q fp16
__device__ __half g_K[NTOK * DH];                  // K fp16
__device__ float  g_Vt[BATCH * DH * SEQ];          // V fp32, [b][d][i]
__device__ __half g_E[(size_t)NTOK * SEQ];         // exp(S) fp16, [b,i,j]
__device__ __half g_Vf[BATCH * DH * SEQ];          // V' = diag(c) V, fp16, [b][d][i]
__device__ float g_psum[BATCH * ITILES * SEQ];
__device__ float g_ci[BATCH * SEQ];

// ---------------- helpers ----------------
__device__ __forceinline__ uint32_t s_u32(const void* p) {
    uint32_t a;
    asm("{ .reg .u64 t; cvta.to.shared.u64 t, %1; cvt.u32.u64 %0, t; }" : "=r"(a) : "l"(p));
    return a;
}
#define LDSM4(r0, r1, r2, r3, addr) \
    asm volatile("ldmatrix.sync.aligned.m8n8.x4.shared.b16 {%0,%1,%2,%3}, [%4];" \
                 : "=r"(r0), "=r"(r1), "=r"(r2), "=r"(r3) : "r"(addr))
#define CPA16(dst, src) \
    asm volatile("cp.async.cg.shared.global [%0], [%1], 16;" :: "r"(dst), "l"(src))
#define CPA_COMMIT() asm volatile("cp.async.commit_group;" ::: "memory")
#define CPA_WAIT2()  asm volatile("cp.async.wait_group 2;" ::: "memory")
#define CPA_WAIT1()  asm volatile("cp.async.wait_group 1;" ::: "memory")
#define CPA_WAIT0()  asm volatile("cp.async.wait_group 0;" ::: "memory")

__device__ __forceinline__ void mma_f16(float* c, const uint32_t* a, const uint32_t* b) {
    asm volatile(
        "mma.sync.aligned.m16n8k16.row.col.f32.f16.f16.f32 "
        "{%0,%1,%2,%3}, {%4,%5,%6,%7}, {%8,%9}, {%0,%1,%2,%3};"
        : "+f"(c[0]), "+f"(c[1]), "+f"(c[2]), "+f"(c[3])
        : "r"(a[0]), "r"(a[1]), "r"(a[2]), "r"(a[3]), "r"(b[0]), "r"(b[1]));
}
__device__ __forceinline__ uint32_t pk2(unsigned short a, unsigned short b) {
    return (uint32_t)a | ((uint32_t)b << 16);
}
__device__ __forceinline__ unsigned short h16(float v) {
    return __half_as_ushort(__float2half(v));
}

// ---------------- W -> fp16 transpose ----------------
__global__ __launch_bounds__(256) void split_w_kernel(
    const float* __restrict__ Wq, const float* __restrict__ Wk, const float* __restrict__ Wv) {
    int mt = blockIdx.y;
    const float* W = (mt == 0) ? Wq : (mt == 1) ? Wk : Wv;
    int idx = blockIdx.x * 256 + threadIdx.x;
    int k = idx >> 6, c = idx & 63;
    g_W[(mt * 64 + c) * DM + k] = __float2half(W[k * DH + c]);
}

// ---------------- fused QKV projection: 2-stage, single-fp16 ----------------
// grid 128, block 512 (16 warps 4x4). Stage (46080 B x2): A @0 (18432), B @18432 (27648)
__global__ __launch_bounds__(512) void proj_kernel(
    const float* __restrict__ x, const float* __restrict__ bq,
    const float* __restrict__ bk, const float* __restrict__ bv) {
    extern __shared__ char smem[];
    const uint32_t sbase = s_u32(smem);
    const int tid = threadIdx.x, lane = tid & 31, w = tid >> 5;
    const int row0 = blockIdx.x * 128;
    const int bb = row0 >> 11, iloc = row0 & 2047;

    const int wm = w & 3, wn = w >> 2;          // rows wm*32, cols wn*48
    float acc[2][6][4];
    #pragma unroll
    for (int i = 0; i < 2; i++)
        #pragma unroll
        for (int j = 0; j < 6; j++)
            #pragma unroll
            for (int q = 0; q < 4; q++) acc[i][j][q] = 0.f;

    const int xr_r = tid >> 2, xr_c = (tid & 3) * 16;

    auto ldx = [&](int kc, float4* xr) {
        const float4* src = (const float4*)(x + (size_t)(row0 + xr_r) * DM + kc * 64 + xr_c);
        xr[0] = src[0]; xr[1] = src[1]; xr[2] = src[2]; xr[3] = src[3];
    };
    auto convA = [&](const float4* xr, int st) {
        __half* A = (__half*)(smem + st * 46080);
        unsigned short hs[16];
        #pragma unroll
        for (int q = 0; q < 4; q++) {
            float4 v = xr[q];
            hs[q*4+0] = h16(v.x); hs[q*4+1] = h16(v.y);
            hs[q*4+2] = h16(v.z); hs[q*4+3] = h16(v.w);
        }
        uint4* dh = (uint4*)(A + xr_r * 72 + xr_c);
        dh[0] = make_uint4(pk2(hs[0],hs[1]), pk2(hs[2],hs[3]), pk2(hs[4],hs[5]), pk2(hs[6],hs[7]));
        dh[1] = make_uint4(pk2(hs[8],hs[9]), pk2(hs[10],hs[11]), pk2(hs[12],hs[13]), pk2(hs[14],hs[15]));
    };
    auto ldW = [&](int kc, int st) {
        uint32_t bw = sbase + st * 46080 + 18432;
        #pragma unroll
        for (int p = 0; p < 3; p++) {
            int lin = p * 512 + tid, r = lin >> 3, q = lin & 7;
            CPA16(bw + (uint32_t)(r * 144 + q * 16),
                  (const char*)g_W + ((size_t)r * DM + kc * 64) * 2 + q * 16);
        }
        CPA_COMMIT();
    };

    float4 xr[4];
    ldx(0, xr);
    ldW(0, 0);
    convA(xr, 0);
    CPA_WAIT0();
    __syncthreads();

    for (int c = 0; c < 16; c++) {
        const int cur = c & 1;
        if (c < 15) { ldx(c + 1, xr); ldW(c + 1, cur ^ 1); }

        const uint32_t S = sbase + cur * 46080;
        const uint32_t sA = S, sB = S + 18432;
        #pragma unroll
        for (int ks = 0; ks < 4; ks++) {
            const int k0 = ks * 16;
            uint32_t a[2][4];
            #pragma unroll
            for (int mf = 0; mf < 2; mf++) {
                uint32_t off = (uint32_t)((wm * 32 + mf * 16 + (lane & 15)) * 72 +
                                          k0 + ((lane >> 4) << 3)) * 2;
                LDSM4(a[mf][0], a[mf][1], a[mf][2], a[mf][3], sA + off);
            }
            uint32_t b[6][2];
            #pragma unroll
            for (int nb = 0; nb < 3; nb++) {
                uint32_t off = (uint32_t)((wn * 48 + nb * 16 + (lane & 7) + ((lane >> 4) << 3)) * 72 +
                                          k0 + (((lane >> 3) & 1) << 3)) * 2;
                LDSM4(b[2*nb][0], b[2*nb][1], b[2*nb+1][0], b[2*nb+1][1], sB + off);
            }
            #pragma unroll
            for (int mf = 0; mf < 2; mf++)
                #pragma unroll
                for (int nf = 0; nf < 6; nf++)
                    mma_f16(acc[mf][nf], a[mf], b[nf]);
        }
        if (c < 15) { convA(xr, cur ^ 1); CPA_WAIT0(); }
        __syncthreads();
    }

    // epilogue: Q, K single fp16 direct; V staged fp32 transposed
    float* sV = (float*)smem;     // [64][132] fp32 = 33792 B
    #pragma unroll
    for (int mf = 0; mf < 2; mf++)
        #pragma unroll
        for (int nf = 0; nf < 6; nf++) {
            int gc = wn * 48 + nf * 8 + (lane & 3) * 2;
            int mt = gc >> 6, cm = gc & 63;
            int r0 = wm * 32 + mf * 16 + (lane >> 2);
            #pragma unroll
            for (int h = 0; h < 2; h++) {
                int rl = r0 + h * 8;
                float v0 = acc[mf][nf][h * 2 + 0], v1 = acc[mf][nf][h * 2 + 1];
                if (mt == 0) {
                    size_t o = (size_t)(row0 + rl) * DH + cm;
                    *(uint32_t*)(g_Q + o) = pk2(h16(v0 + bq[cm]), h16(v1 + bq[cm + 1]));
                } else if (mt == 1) {
                    size_t o = (size_t)(row0 + rl) * DH + cm;
                    *(uint32_t*)(g_K + o) = pk2(h16(v0 + bk[cm]), h16(v1 + bk[cm + 1]));
                } else {
                    sV[cm * 132 + rl]       = v0 + bv[cm];
                    sV[(cm + 1) * 132 + rl] = v1 + bv[cm + 1];
                }
            }
        }
    __syncthreads();
    #pragma unroll
    for (int p = 0; p < 4; p++) {
        int lin = p * 512 + tid, r = lin >> 5, q4 = lin & 31;
        *(float4*)(g_Vt + (size_t)(bb * 64 + r) * SEQ + iloc + q4 * 4) =
            *(float4*)(sV + r * 132 + q4 * 4);
    }
}

// ---------------- scores -> E = exp(S) (fp16) + column partial sums ----------------
// grid (16,16,8), block 256. smem: Q,K [128][72]h (36864 B); reused as Est fp16 pitch 136.
__global__ __launch_bounds__(256) void scores_kernel() {
    extern __shared__ char smem[];
    __shared__ float sred[256];
    const int tid = threadIdx.x, lane = tid & 31, w = tid >> 5;
    const int jt = blockIdx.x, it = blockIdx.y, bb = blockIdx.z;
    const int i0 = it * 128, j0 = jt * 128;
    const uint32_t sbase = s_u32(smem);

    {
        const __half* src[2] = { g_Q, g_K };
        #pragma unroll
        for (int a = 0; a < 2; a++) {
            const int rb = bb * SEQ + ((a == 0) ? i0 : j0);
            #pragma unroll
            for (int p = 0; p < 4; p++) {
                int lin = p * 256 + tid, r = lin >> 3, q = lin & 7;
                CPA16(sbase + a * 18432 + (uint32_t)(r * 144 + q * 16),
                      (const char*)src[a] + ((size_t)(rb + r) * DH) * 2 + q * 16);
            }
        }
        CPA_COMMIT(); CPA_WAIT0();
    }
    __syncthreads();

    const uint32_t sQ = sbase, sK = sbase + 18432;
    const int wm = w & 1, wn = w >> 1;          // rows wm*64, cols wn*32
    float acc[4][4][4];
    #pragma unroll
    for (int i = 0; i < 4; i++)
        #pragma unroll
        for (int j = 0; j < 4; j++)
            #pragma unroll
            for (int q = 0; q < 4; q++) acc[i][j][q] = 0.f;

    #pragma unroll
    for (int ks = 0; ks < 4; ks++) {
        const int k0 = ks * 16;
        uint32_t a[4][4];
        #pragma unroll
        for (int mf = 0; mf < 4; mf++) {
            uint32_t off = (uint32_t)((wm * 64 + mf * 16 + (lane & 15)) * 72 +
                                      k0 + ((lane >> 4) << 3)) * 2;
            LDSM4(a[mf][0], a[mf][1], a[mf][2], a[mf][3], sQ + off);
        }
        uint32_t b[4][2];
        #pragma unroll
        for (int nb = 0; nb < 2; nb++) {
            uint32_t off = (uint32_t)((wn * 32 + nb * 16 + (lane & 7) + ((lane >> 4) << 3)) * 72 +
                                      k0 + (((lane >> 3) & 1) << 3)) * 2;
            LDSM4(b[2*nb][0], b[2*nb][1], b[2*nb+1][0], b[2*nb+1][1], sK + off);
        }
        #pragma unroll
        for (int mf = 0; mf < 4; mf++)
            #pragma unroll
            for (int nf = 0; nf < 4; nf++)
                mma_f16(acc[mf][nf], a[mf], b[nf]);
    }
    __syncthreads();

    // stage E = exp(S/8) as fp16 (pitch 136 halves)
    __half* Est = (__half*)smem;
    #pragma unroll
    for (int mf = 0; mf < 4; mf++)
        #pragma unroll
        for (int nf = 0; nf < 4; nf++) {
            int col = wn * 32 + nf * 8 + (lane & 3) * 2;
            int r0 = wm * 64 + mf * 16 + (lane >> 2);
            #pragma unroll
            for (int h = 0; h < 2; h++) {
                float e0 = __expf(0.125f * acc[mf][nf][h * 2 + 0]);
                float e1 = __expf(0.125f * acc[mf][nf][h * 2 + 1]);
                *(__half2*)(Est + (r0 + h * 8) * 136 + col) = __floats2half2_rn(e0, e1);
            }
        }
    __syncthreads();
    // coalesced fp16 E store
    #pragma unroll
    for (int p = 0; p < 8; p++) {
        int lin = p * 256 + tid, r = lin >> 4, c8 = lin & 15;
        *(uint4*)((char*)g_E + ((size_t)(bb * SEQ + i0 + r) * SEQ + j0) * 2 + c8 * 16) =
            *(uint4*)((char*)Est + r * 272 + c8 * 16);
    }
    // per-column partial sums (all 256 threads, 2-way row split)
    {
        int col = tid & 127, hf = tid >> 7;
        float s = 0.f;
        #pragma unroll 8
        for (int i = 0; i < 64; i++) s += __half2float(Est[(hf * 64 + i) * 136 + col]);
        sred[tid] = s;
        __syncthreads();
        if (tid < 128)
            g_psum[(bb * ITILES + it) * SEQ + j0 + tid] = sred[tid] + sred[tid + 128];
    }
}

// ---------------- merge psums -> c_j = 1/sum (parallel, coalesced) ----------------
__global__ __launch_bounds__(256) void merge_stats_kernel() {
    int idx = blockIdx.x * 256 + threadIdx.x;   // 16384
    int bb = idx >> 11, j = idx & 2047;
    float s = 0.f;
    #pragma unroll
    for (int it = 0; it < ITILES; it++)
        s += g_psum[(bb * ITILES + it) * SEQ + j];
    g_ci[idx] = 1.0f / s;
}

// ---------------- V' = diag(c) V -> fp16 (float4-vectorized) ----------------
// 1M elements / 4 per thread = 262144 threads. 4 consecutive i share a [b][d] row.
__global__ __launch_bounds__(256) void scale_v_kernel() {
    int t4 = blockIdx.x * 256 + threadIdx.x;      // 0 .. 262143
    int idx = t4 * 4;                             // element index in [b][d][i]
    int bb = idx >> 17, i = idx & 2047;
    float4 v = *(const float4*)(g_Vt + idx);
    float4 c = *(const float4*)(g_ci + bb * SEQ + i);
    __half2 lo = __floats2half2_rn(v.x * c.x, v.y * c.y);
    __half2 hi = __floats2half2_rn(v.z * c.z, v.w * c.w);
    *(uint2*)(g_Vf + idx) = make_uint2(
        pk2(__half_as_ushort(__low2half(lo)), __half_as_ushort(__high2half(lo))),
        pk2(__half_as_ushort(__low2half(hi)), __half_as_ushort(__high2half(hi))));
}

// ---------------- output: 3-stage fp16 GEMM O = E @ V' ----------------
// grid (32,8), block 128 (4 warps 2x2). C [64][64]; 16 j-chunks of 128.
__global__ __launch_bounds__(128) void out_kernel(float* __restrict__ out) {
    extern __shared__ char smem[];
    const int tid = threadIdx.x, lane = tid & 31, w = tid >> 5;
    const int it = blockIdx.x, bb = blockIdx.y;
    const int i0 = it * 64;
    const uint32_t sbase = s_u32(smem);

    const int wm = w & 1, wn = w >> 1;
    float acc[2][4][4];
    #pragma unroll
    for (int i = 0; i < 2; i++)
        #pragma unroll
        for (int j = 0; j < 4; j++)
            #pragma unroll
            for (int q = 0; q < 4; q++) acc[i][j][q] = 0.f;

    const char* Eg = (const char*)g_E;
    const char* Vg = (const char*)g_Vf;

    auto issue = [&](int c) {
        const uint32_t base = sbase + (c % 3) * 34816;
        const int j0 = c * 128;
        #pragma unroll
        for (int p = 0; p < 8; p++) {
            int lin = p * 128 + tid, r = lin >> 4, q = lin & 15;
            CPA16(base + (uint32_t)(r * 272 + q * 16),
                  Eg + ((size_t)(bb * SEQ + i0 + r) * SEQ + j0) * 2 + q * 16);
        }
        #pragma unroll
        for (int p = 0; p < 8; p++) {
            int lin = p * 128 + tid, r = lin >> 4, q = lin & 15;
            CPA16(base + 17408 + (uint32_t)(r * 272 + q * 16),
                  Vg + ((size_t)(bb * 64 + r) * SEQ + j0) * 2 + q * 16);
        }
        CPA_COMMIT();
    };

    issue(0); issue(1);
    for (int c = 0; c < 16; c++) {
        if (c + 2 < 16) { issue(c + 2); CPA_WAIT2(); }
        else if (c + 1 < 16) { CPA_WAIT1(); }
        else { CPA_WAIT0(); }
        __syncthreads();

        const uint32_t base = sbase + (c % 3) * 34816;
        const uint32_t sE = base, sV = base + 17408;
        #pragma unroll
        for (int ks = 0; ks < 8; ks++) {
            const int k0 = ks * 16;
            uint32_t a[2][4];
            #pragma unroll
            for (int mf = 0; mf < 2; mf++) {
                uint32_t off = (uint32_t)((wm * 32 + mf * 16 + (lane & 15)) * 136 +
                                          k0 + ((lane >> 4) << 3)) * 2;
                LDSM4(a[mf][0], a[mf][1], a[mf][2], a[mf][3], sE + off);
            }
            uint32_t b[4][2];
            #pragma unroll
            for (int nb = 0; nb < 2; nb++) {
                uint32_t off = (uint32_t)((wn * 32 + nb * 16 + (lane & 7) + ((lane >> 4) << 3)) * 136 +
                                          k0 + (((lane >> 3) & 1) << 3)) * 2;
                LDSM4(b[2*nb][0], b[2*nb][1], b[2*nb+1][0], b[2*nb+1][1], sV + off);
            }
            #pragma unroll
            for (int mf = 0; mf < 2; mf++)
                #pragma unroll
                for (int nf = 0; nf < 4; nf++)
                    mma_f16(acc[mf][nf], a[mf], b[nf]);
        }
        __syncthreads();
    }

    // epilogue
    float* Ost = (float*)smem;
    #pragma unroll
    for (int mf = 0; mf < 2; mf++)
        #pragma unroll
        for (int nf = 0; nf < 4; nf++) {
            int col = wn * 32 + nf * 8 + (lane & 3) * 2;
            int r0 = wm * 32 + mf * 16 + (lane >> 2);
            #pragma unroll
            for (int h = 0; h < 2; h++) {
                Ost[(r0 + h * 8) * 68 + col]     = acc[mf][nf][h * 2 + 0];
                Ost[(r0 + h * 8) * 68 + col + 1] = acc[mf][nf][h * 2 + 1];
            }
        }
    __syncthreads();
    #pragma unroll
    for (int p = 0; p < 8; p++) {
        int lin = p * 128 + tid, r = lin >> 4, c4 = lin & 15;
        *(float4*)(out + ((size_t)(bb * SEQ + i0 + r)) * DH + c4 * 4) =
            *(float4*)(Ost + r * 68 + c4 * 4);
    }
}

// ---------------- launch ----------------
extern "C" void kernel_launch(void* const* d_in, const int* in_sizes, int n_in,
                              void* d_out, int out_size)
{
    const float* x  = (const float*)d_in[0];
    const float* Wq = (const float*)d_in[1];
    const float* bq = (const float*)d_in[2];
    const float* Wk = (const float*)d_in[3];
    const float* bk = (const float*)d_in[4];
    const float* Wv = (const float*)d_in[5];
    const float* bv = (const float*)d_in[6];
    float* out = (float*)d_out;

    cudaFuncSetAttribute(proj_kernel,   cudaFuncAttributeMaxDynamicSharedMemorySize, 92160);
    cudaFuncSetAttribute(scores_kernel, cudaFuncAttributeMaxDynamicSharedMemorySize, 36864);
    cudaFuncSetAttribute(out_kernel,    cudaFuncAttributeMaxDynamicSharedMemorySize, 104448);

    split_w_kernel<<<dim3(256, 3), 256>>>(Wq, Wk, Wv);
    proj_kernel<<<128, 512, 92160>>>(x, bq, bk, bv);
    scores_kernel<<<dim3(16, 16, 8), 256, 36864>>>();
    merge_stats_kernel<<<64, 256>>>();
    scale_v_kernel<<<1024, 256>>>();
    out_kernel<<<dim3(32, 8), 128, 104448>>>(out);
}